// round 1
// baseline (speedup 1.0000x reference)
#include <cuda_runtime.h>
#include <math.h>

#define N_NODES 100000
#define N_EDGES 1600000
#define C_IN 500
#define HIDDEN 256
#define C_OUT 50
#define K_HALF 5
#define NB_SCAN 391  /* ceil(100000/256) */

// ---------------- scratch (static device globals; no allocation) ----------------
__device__ float g_h[25600000];        // [N, HIDDEN] hidden layer (102.4 MB)
__device__ float g_bufA[5000000];      // [N, C_OUT]
__device__ float g_bufB[5000000];      // [N, C_OUT]
__device__ float g_hidden[5000000];    // [N, C_OUT] accumulator
__device__ float g_dinv[N_NODES];
__device__ int   g_cnt_src[N_NODES];
__device__ int   g_cnt_dst[N_NODES];
__device__ int   g_cursor[N_NODES];
__device__ int   g_rowptr[N_NODES + 1];
__device__ int   g_csr_src[N_EDGES];
__device__ float g_csr_w[N_EDGES];
__device__ int   g_partial[512];

// ---------------- graph preprocessing ----------------
__global__ void zero_kernel() {
    int i = blockIdx.x * blockDim.x + threadIdx.x;
    if (i < N_NODES) { g_cnt_src[i] = 0; g_cnt_dst[i] = 0; g_cursor[i] = 0; }
}

__global__ void count_kernel(const int* __restrict__ ei) {
    int i = blockIdx.x * blockDim.x + threadIdx.x;
    if (i < N_EDGES) {
        atomicAdd(&g_cnt_src[ei[i]], 1);
        atomicAdd(&g_cnt_dst[ei[N_EDGES + i]], 1);
    }
}

__global__ void dinv_kernel() {
    int i = blockIdx.x * blockDim.x + threadIdx.x;
    if (i < N_NODES) {
        int d = g_cnt_src[i];
        g_dinv[i] = d > 0 ? rsqrtf((float)d) : 0.0f;
    }
}

__global__ void scan_partial_kernel() {
    __shared__ int sh[256];
    int i = blockIdx.x * 256 + threadIdx.x;
    int v = (i < N_NODES) ? g_cnt_dst[i] : 0;
    sh[threadIdx.x] = v;
    __syncthreads();
    for (int s = 128; s > 0; s >>= 1) {
        if (threadIdx.x < s) sh[threadIdx.x] += sh[threadIdx.x + s];
        __syncthreads();
    }
    if (threadIdx.x == 0) g_partial[blockIdx.x] = sh[0];
}

__global__ void scan_offsets_kernel() {
    int acc = 0;
    for (int b = 0; b < NB_SCAN; b++) { int v = g_partial[b]; g_partial[b] = acc; acc += v; }
    g_rowptr[N_NODES] = N_EDGES;
}

__global__ void scan_final_kernel() {
    __shared__ int sh[256];
    int i = blockIdx.x * 256 + threadIdx.x;
    int v = (i < N_NODES) ? g_cnt_dst[i] : 0;
    sh[threadIdx.x] = v;
    __syncthreads();
    for (int s = 1; s < 256; s <<= 1) {
        int t = (threadIdx.x >= s) ? sh[threadIdx.x - s] : 0;
        __syncthreads();
        sh[threadIdx.x] += t;
        __syncthreads();
    }
    if (i < N_NODES) g_rowptr[i] = g_partial[blockIdx.x] + sh[threadIdx.x] - v;
}

__global__ void fill_kernel(const int* __restrict__ ei) {
    int i = blockIdx.x * blockDim.x + threadIdx.x;
    if (i < N_EDGES) {
        int s = ei[i], d = ei[N_EDGES + i];
        int pos = g_rowptr[d] + atomicAdd(&g_cursor[d], 1);
        g_csr_src[pos] = s;
        g_csr_w[pos]   = g_dinv[s] * g_dinv[d];
    }
}

// ---------------- GEMM1: g_h = relu(x @ W1 + b1)  [100000x500 * 500x256] ----------------
__global__ void __launch_bounds__(256, 2) gemm1_kernel(
    const float* __restrict__ A, const float* __restrict__ W, const float* __restrict__ bias) {
    __shared__ float sA[8][128];
    __shared__ float sB[8][128];
    const int M = N_NODES, K = C_IN;
    int tid = threadIdx.x;
    int m0 = blockIdx.y * 128;
    int n0 = blockIdx.x * 128;
    int tx = tid & 15, ty = tid >> 4;

    float acc[8][8];
#pragma unroll
    for (int i = 0; i < 8; i++)
#pragma unroll
        for (int j = 0; j < 8; j++) acc[i][j] = 0.0f;

    int a_row = tid >> 1;
    int a_k   = (tid & 1) * 4;
    int b_n   = (tid & 31) * 4;
    int b_k   = tid >> 5;

    for (int k0 = 0; k0 < K; k0 += 8) {
        // load A tile (zero-padded at edges)
        float4 av = make_float4(0.f, 0.f, 0.f, 0.f);
        int gm = m0 + a_row;
        int gk = k0 + a_k;
        if (gm < M) {
            if (gk + 3 < K) {
                av = *(const float4*)(A + (size_t)gm * K + gk);
            } else {
                float t0 = (gk + 0 < K) ? A[(size_t)gm * K + gk + 0] : 0.f;
                float t1 = (gk + 1 < K) ? A[(size_t)gm * K + gk + 1] : 0.f;
                float t2 = (gk + 2 < K) ? A[(size_t)gm * K + gk + 2] : 0.f;
                float t3 = (gk + 3 < K) ? A[(size_t)gm * K + gk + 3] : 0.f;
                av = make_float4(t0, t1, t2, t3);
            }
        }
        sA[a_k + 0][a_row] = av.x;
        sA[a_k + 1][a_row] = av.y;
        sA[a_k + 2][a_row] = av.z;
        sA[a_k + 3][a_row] = av.w;

        // load B tile
        float4 bv = make_float4(0.f, 0.f, 0.f, 0.f);
        int gbk = k0 + b_k;
        if (gbk < K) bv = *(const float4*)(W + (size_t)gbk * HIDDEN + n0 + b_n);
        *(float4*)&sB[b_k][b_n] = bv;
        __syncthreads();

#pragma unroll
        for (int kk = 0; kk < 8; kk++) {
            float4 a0 = *(float4*)&sA[kk][ty * 8];
            float4 a1 = *(float4*)&sA[kk][ty * 8 + 4];
            float4 c0 = *(float4*)&sB[kk][tx * 8];
            float4 c1 = *(float4*)&sB[kk][tx * 8 + 4];
            float ar[8] = {a0.x, a0.y, a0.z, a0.w, a1.x, a1.y, a1.z, a1.w};
            float br[8] = {c0.x, c0.y, c0.z, c0.w, c1.x, c1.y, c1.z, c1.w};
#pragma unroll
            for (int i = 0; i < 8; i++)
#pragma unroll
                for (int j = 0; j < 8; j++) acc[i][j] += ar[i] * br[j];
        }
        __syncthreads();
    }

#pragma unroll
    for (int i = 0; i < 8; i++) {
        int gm = m0 + ty * 8 + i;
        if (gm >= M) continue;
#pragma unroll
        for (int j = 0; j < 8; j++) {
            int gn = n0 + tx * 8 + j;
            float v = acc[i][j] + bias[gn];
            g_h[(size_t)gm * HIDDEN + gn] = v > 0.f ? v : 0.f;
        }
    }
}

// ---------------- GEMM2: bufA = g_h @ W2 + b2; hidden = temp[0]*bufA ----------------
__global__ void __launch_bounds__(256) gemm2_kernel(
    const float* __restrict__ W2, const float* __restrict__ b2, const float* __restrict__ temp) {
    __shared__ float shH[64 * 64];     // 64 rows x 64 k
    __shared__ float shW[64 * C_OUT];  // 64 k x 50 cols
    int tid = threadIdx.x;
    int r0 = blockIdx.x * 64;
    int lane = tid & 31, rg = tid >> 5;

    float acc0[8], acc1[8];
#pragma unroll
    for (int i = 0; i < 8; i++) { acc0[i] = 0.f; acc1[i] = 0.f; }

    for (int kc = 0; kc < HIDDEN; kc += 64) {
#pragma unroll
        for (int j = 0; j < 16; j++) {
            int idx = tid + j * 256;
            int r = idx >> 6, k = idx & 63;
            int gr = r0 + r;
            shH[idx] = (gr < N_NODES) ? g_h[(size_t)gr * HIDDEN + kc + k] : 0.f;
        }
        for (int idx = tid; idx < 64 * C_OUT; idx += 256) {
            int k = idx / C_OUT, c = idx % C_OUT;
            shW[idx] = W2[(size_t)(kc + k) * C_OUT + c];
        }
        __syncthreads();
#pragma unroll 4
        for (int k = 0; k < 64; k++) {
            float w0 = shW[k * C_OUT + lane];
            float w1 = (lane < C_OUT - 32) ? shW[k * C_OUT + lane + 32] : 0.f;
#pragma unroll
            for (int i = 0; i < 8; i++) {
                float a = shH[(rg * 8 + i) * 64 + k];
                acc0[i] += a * w0;
                acc1[i] += a * w1;
            }
        }
        __syncthreads();
    }

    float t0 = temp[0];
#pragma unroll
    for (int i = 0; i < 8; i++) {
        int r = r0 + rg * 8 + i;
        if (r >= N_NODES) continue;
        float v0 = acc0[i] + b2[lane];
        g_bufA[(size_t)r * C_OUT + lane] = v0;
        g_hidden[(size_t)r * C_OUT + lane] = t0 * v0;
        if (lane < C_OUT - 32) {
            float v1 = acc1[i] + b2[lane + 32];
            g_bufA[(size_t)r * C_OUT + lane + 32] = v1;
            g_hidden[(size_t)r * C_OUT + lane + 32] = t0 * v1;
        }
    }
}

// ---------------- pull propagation: out[d] = sum_in_edges w * in[src]  ----------------
// dir 0: bufA -> bufB ; dir 1: bufB -> bufA. One warp per dst node, no atomics.
__global__ void __launch_bounds__(256) pull_kernel(int dir) {
    const float* __restrict__ xin  = dir ? g_bufB : g_bufA;
    float* __restrict__       xout = dir ? g_bufA : g_bufB;
    int node = (blockIdx.x * blockDim.x + threadIdx.x) >> 5;
    int lane = threadIdx.x & 31;
    if (node >= N_NODES) return;
    int beg = g_rowptr[node], end = g_rowptr[node + 1];
    float a0 = 0.f, a1 = 0.f;
    for (int e = beg; e < end; e++) {
        int s = g_csr_src[e];
        float w = g_csr_w[e];
        const float* row = xin + (size_t)s * C_OUT;
        a0 += w * row[lane];
        float v1 = (lane < C_OUT - 32) ? row[lane + 32] : 0.f;
        a1 += w * v1;
    }
    float* orow = xout + (size_t)node * C_OUT;
    orow[lane] = a0;
    if (lane < C_OUT - 32) orow[lane + 32] = a1;
}

// ---------------- hidden += temp[kidx] * bufA ----------------
__global__ void axpy_kernel(const float* __restrict__ temp, int kidx) {
    float t = temp[kidx];
    int i = blockIdx.x * blockDim.x + threadIdx.x;
    if (i < N_NODES * C_OUT) g_hidden[i] += t * g_bufA[i];
}

// ---------------- log_softmax over rows of 50 ----------------
__global__ void __launch_bounds__(256) logsoftmax_kernel(float* __restrict__ out) {
    int node = (blockIdx.x * blockDim.x + threadIdx.x) >> 5;
    int lane = threadIdx.x & 31;
    if (node >= N_NODES) return;
    const float* row = g_hidden + (size_t)node * C_OUT;
    float v0 = row[lane];
    float v1 = (lane < C_OUT - 32) ? row[lane + 32] : -INFINITY;
    float m = fmaxf(v0, v1);
#pragma unroll
    for (int o = 16; o > 0; o >>= 1) m = fmaxf(m, __shfl_xor_sync(0xffffffffu, m, o));
    float s = expf(v0 - m) + ((lane < C_OUT - 32) ? expf(v1 - m) : 0.f);
#pragma unroll
    for (int o = 16; o > 0; o >>= 1) s += __shfl_xor_sync(0xffffffffu, s, o);
    float l = m + logf(s);
    float* orow = out + (size_t)node * C_OUT;
    orow[lane] = v0 - l;
    if (lane < C_OUT - 32) orow[lane + 32] = v1 - l;
}

// ---------------- launch ----------------
extern "C" void kernel_launch(void* const* d_in, const int* in_sizes, int n_in,
                              void* d_out, int out_size) {
    const float* x    = (const float*)d_in[0];
    const int*   ei   = (const int*)d_in[1];
    const float* W1   = (const float*)d_in[2];
    const float* b1   = (const float*)d_in[3];
    const float* W2   = (const float*)d_in[4];
    const float* b2   = (const float*)d_in[5];
    const float* temp = (const float*)d_in[6];
    float* out = (float*)d_out;

    int nb_nodes = (N_NODES + 255) / 256;
    int nb_edges = (N_EDGES + 255) / 256;

    // CSR build (dst-sorted) + degree norm
    zero_kernel<<<nb_nodes, 256>>>();
    count_kernel<<<nb_edges, 256>>>(ei);
    dinv_kernel<<<nb_nodes, 256>>>();
    scan_partial_kernel<<<NB_SCAN, 256>>>();
    scan_offsets_kernel<<<1, 1>>>();
    scan_final_kernel<<<NB_SCAN, 256>>>();
    fill_kernel<<<nb_edges, 256>>>(ei);

    // MLP
    dim3 g1(HIDDEN / 128, (N_NODES + 127) / 128);
    gemm1_kernel<<<g1, 256>>>(x, W1, b1);
    gemm2_kernel<<<(N_NODES + 63) / 64, 256>>>(W2, b2, temp);

    // 5 x (two propagation hops) + accumulate
    int pull_grid = (N_NODES * 32 + 255) / 256;
    int nb_feat = (N_NODES * C_OUT + 255) / 256;
    for (int k = 0; k < K_HALF; k++) {
        pull_kernel<<<pull_grid, 256>>>(0);  // bufA -> bufB
        pull_kernel<<<pull_grid, 256>>>(1);  // bufB -> bufA
        axpy_kernel<<<nb_feat, 256>>>(temp, k + 1);
    }

    logsoftmax_kernel<<<pull_grid, 256>>>(out);
}

// round 3
// speedup vs baseline: 1.6742x; 1.6742x over previous
#include <cuda_runtime.h>
#include <cstdint>
#include <math.h>

#define N_NODES 100000
#define N_EDGES 1600000
#define C_IN 500
#define HIDDEN 256
#define C_OUT 50
#define K_HALF 5
#define NB_SCAN 391  /* ceil(100000/256) */

// ---------------- scratch (static device globals; no allocation) ----------------
__device__ float g_h[25600000];        // [N, HIDDEN]
__device__ float g_bufA[5000000];      // [N, C_OUT]
__device__ float g_bufB[5000000];      // [N, C_OUT]
__device__ float g_hidden[5000000];    // [N, C_OUT]
__device__ float g_dinv[N_NODES];
__device__ int   g_cnt_src[N_NODES];
__device__ int   g_cnt_dst[N_NODES];
__device__ int   g_cursor[N_NODES];
__device__ int   g_rowptr[N_NODES + 1];
__device__ int   g_csr_src[N_EDGES];
__device__ float g_csr_w[N_EDGES];
__device__ int   g_partial[512];

// ---------------- graph preprocessing ----------------
__global__ void zero_kernel() {
    int i = blockIdx.x * blockDim.x + threadIdx.x;
    if (i < N_NODES) { g_cnt_src[i] = 0; g_cnt_dst[i] = 0; g_cursor[i] = 0; }
}

__global__ void count_kernel(const int* __restrict__ ei) {
    int i = blockIdx.x * blockDim.x + threadIdx.x;
    if (i < N_EDGES) {
        atomicAdd(&g_cnt_src[ei[i]], 1);
        atomicAdd(&g_cnt_dst[ei[N_EDGES + i]], 1);
    }
}

__global__ void dinv_kernel() {
    int i = blockIdx.x * blockDim.x + threadIdx.x;
    if (i < N_NODES) {
        int d = g_cnt_src[i];
        g_dinv[i] = d > 0 ? rsqrtf((float)d) : 0.0f;
    }
}

__global__ void scan_partial_kernel() {
    __shared__ int sh[256];
    int i = blockIdx.x * 256 + threadIdx.x;
    int v = (i < N_NODES) ? g_cnt_dst[i] : 0;
    sh[threadIdx.x] = v;
    __syncthreads();
    for (int s = 128; s > 0; s >>= 1) {
        if (threadIdx.x < s) sh[threadIdx.x] += sh[threadIdx.x + s];
        __syncthreads();
    }
    if (threadIdx.x == 0) g_partial[blockIdx.x] = sh[0];
}

__global__ void scan_offsets_kernel() {
    int acc = 0;
    for (int b = 0; b < NB_SCAN; b++) { int v = g_partial[b]; g_partial[b] = acc; acc += v; }
    g_rowptr[N_NODES] = N_EDGES;
}

__global__ void scan_final_kernel() {
    __shared__ int sh[256];
    int i = blockIdx.x * 256 + threadIdx.x;
    int v = (i < N_NODES) ? g_cnt_dst[i] : 0;
    sh[threadIdx.x] = v;
    __syncthreads();
    for (int s = 1; s < 256; s <<= 1) {
        int t = (threadIdx.x >= s) ? sh[threadIdx.x - s] : 0;
        __syncthreads();
        sh[threadIdx.x] += t;
        __syncthreads();
    }
    if (i < N_NODES) g_rowptr[i] = g_partial[blockIdx.x] + sh[threadIdx.x] - v;
}

__global__ void fill_kernel(const int* __restrict__ ei) {
    int i = blockIdx.x * blockDim.x + threadIdx.x;
    if (i < N_EDGES) {
        int s = ei[i], d = ei[N_EDGES + i];
        int pos = g_rowptr[d] + atomicAdd(&g_cursor[d], 1);
        g_csr_src[pos] = s;
        g_csr_w[pos]   = g_dinv[s] * g_dinv[d];
    }
}

// ---------------- GEMM1 (tf32 tensor cores): g_h = relu(x @ W1 + b1) ----------------
// BM=64, BN=256 (full width -> x read once), BK=32, cp.async double buffer.
#define SA_STRIDE 36
#define SB_STRIDE 264
#define A_SZ (64 * SA_STRIDE)   /* 2304 floats */
#define B_SZ (32 * SB_STRIDE)   /* 8448 floats */
#define GEMM1_SMEM (2 * (A_SZ + B_SZ) * 4)  /* 86016 bytes */

__device__ __forceinline__ unsigned int f2tf32(float f) {
    unsigned int r;
    asm volatile("cvt.rna.tf32.f32 %0, %1;" : "=r"(r) : "f"(f));
    return r;
}

__global__ void __launch_bounds__(256) gemm1_tc_kernel(
    const float* __restrict__ A, const float* __restrict__ W, const float* __restrict__ bias) {
    extern __shared__ float smem[];
    float* sAb[2] = { smem, smem + A_SZ + B_SZ };
    float* sBb[2] = { smem + A_SZ, smem + 2 * A_SZ + B_SZ };

    const int tid = threadIdx.x;
    const int m0 = blockIdx.x * 64;
    const int wid = tid >> 5, lane = tid & 31;
    const int warp_m = wid >> 2, warp_n = wid & 3;   // 2 x 4 warps
    const int r = lane >> 2, c = lane & 3;

    float acc[2][8][4];
#pragma unroll
    for (int mt = 0; mt < 2; mt++)
#pragma unroll
        for (int nt = 0; nt < 8; nt++)
#pragma unroll
            for (int i = 0; i < 4; i++) acc[mt][nt][i] = 0.0f;

    auto load_tiles = [&](int buf, int k0) {
        // A tile: 64 rows x 32 k (8 float4 per row) = 512 float4
#pragma unroll
        for (int j = 0; j < 2; j++) {
            int idx = tid + j * 256;
            int row = idx >> 3, kv = (idx & 7) * 4;
            int gm = m0 + row, gk = k0 + kv;
            int v = (gm < N_NODES) && (gk < C_IN);
            const float* src = A + (size_t)(v ? gm : 0) * C_IN + (v ? gk : 0);
            unsigned int dst = (unsigned int)__cvta_generic_to_shared(sAb[buf] + row * SA_STRIDE + kv);
            int sz = v ? 16 : 0;
            asm volatile("cp.async.cg.shared.global [%0], [%1], 16, %2;\n"
                         :: "r"(dst), "l"(src), "r"(sz));
        }
        // B tile: 32 k-rows x 256 n (64 float4 per row) = 2048 float4
#pragma unroll
        for (int j = 0; j < 8; j++) {
            int idx = tid + j * 256;
            int krow = idx >> 6, nv = (idx & 63) * 4;
            int gk = k0 + krow;
            int v = (gk < C_IN);
            const float* src = W + (size_t)(v ? gk : 0) * HIDDEN + nv;
            unsigned int dst = (unsigned int)__cvta_generic_to_shared(sBb[buf] + krow * SB_STRIDE + nv);
            int sz = v ? 16 : 0;
            asm volatile("cp.async.cg.shared.global [%0], [%1], 16, %2;\n"
                         :: "r"(dst), "l"(src), "r"(sz));
        }
        asm volatile("cp.async.commit_group;\n");
    };

    const int NIT = (C_IN + 31) / 32;   // 16
    load_tiles(0, 0);

    for (int it = 0; it < NIT; it++) {
        if (it + 1 < NIT) {
            load_tiles((it + 1) & 1, (it + 1) * 32);
            asm volatile("cp.async.wait_group 1;\n");
        } else {
            asm volatile("cp.async.wait_group 0;\n");
        }
        __syncthreads();

        const float* sA = sAb[it & 1];
        const float* sB = sBb[it & 1];

#pragma unroll
        for (int kk = 0; kk < 4; kk++) {
            const int kb = kk * 8;
            unsigned int af[2][4], bf[8][2];
#pragma unroll
            for (int mt = 0; mt < 2; mt++) {
                const float* base = sA + (warp_m * 32 + mt * 16 + r) * SA_STRIDE + kb + c;
                af[mt][0] = f2tf32(base[0]);
                af[mt][1] = f2tf32(base[8 * SA_STRIDE]);
                af[mt][2] = f2tf32(base[4]);
                af[mt][3] = f2tf32(base[8 * SA_STRIDE + 4]);
            }
#pragma unroll
            for (int nt = 0; nt < 8; nt++) {
                const float* base = sB + (kb + c) * SB_STRIDE + warp_n * 64 + nt * 8 + r;
                bf[nt][0] = f2tf32(base[0]);
                bf[nt][1] = f2tf32(base[4 * SB_STRIDE]);
            }
#pragma unroll
            for (int mt = 0; mt < 2; mt++)
#pragma unroll
                for (int nt = 0; nt < 8; nt++) {
                    asm volatile(
                        "mma.sync.aligned.m16n8k8.row.col.f32.tf32.tf32.f32 "
                        "{%0,%1,%2,%3}, {%4,%5,%6,%7}, {%8,%9}, {%0,%1,%2,%3};\n"
                        : "+f"(acc[mt][nt][0]), "+f"(acc[mt][nt][1]),
                          "+f"(acc[mt][nt][2]), "+f"(acc[mt][nt][3])
                        : "r"(af[mt][0]), "r"(af[mt][1]), "r"(af[mt][2]), "r"(af[mt][3]),
                          "r"(bf[nt][0]), "r"(bf[nt][1]));
                }
        }
        __syncthreads();
    }

    // epilogue: bias + relu, float2 stores
#pragma unroll
    for (int mt = 0; mt < 2; mt++) {
#pragma unroll
        for (int nt = 0; nt < 8; nt++) {
            int gn = warp_n * 64 + nt * 8 + c * 2;
            float2 bv = *(const float2*)(bias + gn);
            int gm0 = m0 + warp_m * 32 + mt * 16 + r;
            if (gm0 < N_NODES) {
                float2 o;
                o.x = fmaxf(acc[mt][nt][0] + bv.x, 0.f);
                o.y = fmaxf(acc[mt][nt][1] + bv.y, 0.f);
                *(float2*)(g_h + (size_t)gm0 * HIDDEN + gn) = o;
            }
            int gm1 = gm0 + 8;
            if (gm1 < N_NODES) {
                float2 o;
                o.x = fmaxf(acc[mt][nt][2] + bv.x, 0.f);
                o.y = fmaxf(acc[mt][nt][3] + bv.y, 0.f);
                *(float2*)(g_h + (size_t)gm1 * HIDDEN + gn) = o;
            }
        }
    }
}

// ---------------- GEMM2: bufA = g_h @ W2 + b2; hidden = temp[0]*bufA ----------------
__global__ void __launch_bounds__(256) gemm2_kernel(
    const float* __restrict__ W2, const float* __restrict__ b2, const float* __restrict__ temp) {
    __shared__ float shH[64 * 64];
    __shared__ float shW[64 * C_OUT];
    int tid = threadIdx.x;
    int r0 = blockIdx.x * 64;
    int lane = tid & 31, rg = tid >> 5;

    float acc0[8], acc1[8];
#pragma unroll
    for (int i = 0; i < 8; i++) { acc0[i] = 0.f; acc1[i] = 0.f; }

    for (int kc = 0; kc < HIDDEN; kc += 64) {
#pragma unroll
        for (int j = 0; j < 16; j++) {
            int idx = tid + j * 256;
            int r = idx >> 6, k = idx & 63;
            int gr = r0 + r;
            shH[idx] = (gr < N_NODES) ? g_h[(size_t)gr * HIDDEN + kc + k] : 0.f;
        }
        for (int idx = tid; idx < 64 * C_OUT; idx += 256) {
            int k = idx / C_OUT, cc = idx % C_OUT;
            shW[idx] = W2[(size_t)(kc + k) * C_OUT + cc];
        }
        __syncthreads();
#pragma unroll 4
        for (int k = 0; k < 64; k++) {
            float w0 = shW[k * C_OUT + lane];
            float w1 = (lane < C_OUT - 32) ? shW[k * C_OUT + lane + 32] : 0.f;
#pragma unroll
            for (int i = 0; i < 8; i++) {
                float a = shH[(rg * 8 + i) * 64 + k];
                acc0[i] += a * w0;
                acc1[i] += a * w1;
            }
        }
        __syncthreads();
    }

    float t0 = temp[0];
#pragma unroll
    for (int i = 0; i < 8; i++) {
        int r = r0 + rg * 8 + i;
        if (r >= N_NODES) continue;
        float v0 = acc0[i] + b2[lane];
        g_bufA[(size_t)r * C_OUT + lane] = v0;
        g_hidden[(size_t)r * C_OUT + lane] = t0 * v0;
        if (lane < C_OUT - 32) {
            float v1 = acc1[i] + b2[lane + 32];
            g_bufA[(size_t)r * C_OUT + lane + 32] = v1;
            g_hidden[(size_t)r * C_OUT + lane + 32] = t0 * v1;
        }
    }
}

// ---------------- pull hop 1: bufB[d] = sum w * bufA[src] ----------------
__global__ void __launch_bounds__(256) pull1_kernel() {
    int node = (blockIdx.x * blockDim.x + threadIdx.x) >> 5;
    int lane = threadIdx.x & 31;
    if (node >= N_NODES) return;
    int beg = g_rowptr[node], end = g_rowptr[node + 1];
    float a0 = 0.f, a1 = 0.f;
    for (int e = beg; e < end; e++) {
        int s = g_csr_src[e];
        float w = g_csr_w[e];
        const float* row = g_bufA + (size_t)s * C_OUT;
        a0 += w * row[lane];
        float v1 = (lane < C_OUT - 32) ? row[lane + 32] : 0.f;
        a1 += w * v1;
    }
    float* orow = g_bufB + (size_t)node * C_OUT;
    orow[lane] = a0;
    if (lane < C_OUT - 32) orow[lane + 32] = a1;
}

// ---------------- pull hop 2 fused with axpy: bufA[d]=sum w*bufB[src]; hidden += t*bufA ----------------
__global__ void __launch_bounds__(256) pull2_kernel(const float* __restrict__ temp, int kidx) {
    int node = (blockIdx.x * blockDim.x + threadIdx.x) >> 5;
    int lane = threadIdx.x & 31;
    if (node >= N_NODES) return;
    float t = temp[kidx];
    int beg = g_rowptr[node], end = g_rowptr[node + 1];
    float a0 = 0.f, a1 = 0.f;
    for (int e = beg; e < end; e++) {
        int s = g_csr_src[e];
        float w = g_csr_w[e];
        const float* row = g_bufB + (size_t)s * C_OUT;
        a0 += w * row[lane];
        float v1 = (lane < C_OUT - 32) ? row[lane + 32] : 0.f;
        a1 += w * v1;
    }
    float* orow = g_bufA + (size_t)node * C_OUT;
    float* hrow = g_hidden + (size_t)node * C_OUT;
    orow[lane] = a0;
    hrow[lane] += t * a0;
    if (lane < C_OUT - 32) {
        orow[lane + 32] = a1;
        hrow[lane + 32] += t * a1;
    }
}

// ---------------- log_softmax over rows of 50 ----------------
__global__ void __launch_bounds__(256) logsoftmax_kernel(float* __restrict__ out) {
    int node = (blockIdx.x * blockDim.x + threadIdx.x) >> 5;
    int lane = threadIdx.x & 31;
    if (node >= N_NODES) return;
    const float* row = g_hidden + (size_t)node * C_OUT;
    float v0 = row[lane];
    float v1 = (lane < C_OUT - 32) ? row[lane + 32] : -INFINITY;
    float m = fmaxf(v0, v1);
#pragma unroll
    for (int o = 16; o > 0; o >>= 1) m = fmaxf(m, __shfl_xor_sync(0xffffffffu, m, o));
    float s = expf(v0 - m) + ((lane < C_OUT - 32) ? expf(v1 - m) : 0.f);
#pragma unroll
    for (int o = 16; o > 0; o >>= 1) s += __shfl_xor_sync(0xffffffffu, s, o);
    float l = m + logf(s);
    float* orow = out + (size_t)node * C_OUT;
    orow[lane] = v0 - l;
    if (lane < C_OUT - 32) orow[lane + 32] = v1 - l;
}

// ---------------- launch ----------------
extern "C" void kernel_launch(void* const* d_in, const int* in_sizes, int n_in,
                              void* d_out, int out_size) {
    const float* x    = (const float*)d_in[0];
    const int*   ei   = (const int*)d_in[1];
    const float* W1   = (const float*)d_in[2];
    const float* b1   = (const float*)d_in[3];
    const float* W2   = (const float*)d_in[4];
    const float* b2   = (const float*)d_in[5];
    const float* temp = (const float*)d_in[6];
    float* out = (float*)d_out;

    int nb_nodes = (N_NODES + 255) / 256;
    int nb_edges = (N_EDGES + 255) / 256;

    // CSR build (dst-sorted) + degree norm
    zero_kernel<<<nb_nodes, 256>>>();
    count_kernel<<<nb_edges, 256>>>(ei);
    dinv_kernel<<<nb_nodes, 256>>>();
    scan_partial_kernel<<<NB_SCAN, 256>>>();
    scan_offsets_kernel<<<1, 1>>>();
    scan_final_kernel<<<NB_SCAN, 256>>>();
    fill_kernel<<<nb_edges, 256>>>(ei);

    // MLP
    static int smem_set = 0;
    if (!smem_set) {
        cudaFuncSetAttribute(gemm1_tc_kernel, cudaFuncAttributeMaxDynamicSharedMemorySize, GEMM1_SMEM);
        smem_set = 1;
    }
    gemm1_tc_kernel<<<(N_NODES + 63) / 64, 256, GEMM1_SMEM>>>(x, W1, b1);
    gemm2_kernel<<<(N_NODES + 63) / 64, 256>>>(W2, b2, temp);

    // 5 x (two propagation hops), axpy fused into hop 2
    int pull_grid = (N_NODES * 32 + 255) / 256;
    for (int k = 0; k < K_HALF; k++) {
        pull1_kernel<<<pull_grid, 256>>>();
        pull2_kernel<<<pull_grid, 256>>>(temp, k + 1);
    }

    logsoftmax_kernel<<<pull_grid, 256>>>(out);
}

// round 4
// speedup vs baseline: 1.7783x; 1.0622x over previous
#include <cuda_runtime.h>
#include <cuda_fp16.h>
#include <cstdint>
#include <math.h>

#define N_NODES 100000
#define N_EDGES 1600000
#define C_IN 500
#define HIDDEN 256
#define C_OUT 50
#define C_PAD 64            /* padded fp16 row: 64 halves = 128 bytes, line-aligned */
#define K_HALF 5
#define NB_SCAN 391  /* ceil(100000/256) */

// ---------------- scratch (static device globals; no allocation) ----------------
__device__ float  g_h[25600000];           // [N, HIDDEN]
__device__ __half g_bufA[N_NODES * C_PAD]; // [N, 64] fp16 padded
__device__ __half g_bufB[N_NODES * C_PAD]; // [N, 64] fp16 padded
__device__ float  g_hidden[5000000];       // [N, C_OUT] fp32 accumulator
__device__ float  g_dinv[N_NODES];
__device__ int    g_cnt_src[N_NODES];
__device__ int    g_cnt_dst[N_NODES];
__device__ int    g_cursor[N_NODES];
__device__ int    g_rowptr[N_NODES + 1];
__device__ int2   g_csr[N_EDGES];          // (src, w as float bits)
__device__ int    g_partial[512];

// ---------------- graph preprocessing ----------------
__global__ void zero_kernel() {
    int i = blockIdx.x * blockDim.x + threadIdx.x;
    if (i < N_NODES) { g_cnt_src[i] = 0; g_cnt_dst[i] = 0; g_cursor[i] = 0; }
}

__global__ void count_kernel(const int* __restrict__ ei) {
    int i = blockIdx.x * blockDim.x + threadIdx.x;
    if (i < N_EDGES) {
        atomicAdd(&g_cnt_src[ei[i]], 1);
        atomicAdd(&g_cnt_dst[ei[N_EDGES + i]], 1);
    }
}

__global__ void dinv_kernel() {
    int i = blockIdx.x * blockDim.x + threadIdx.x;
    if (i < N_NODES) {
        int d = g_cnt_src[i];
        g_dinv[i] = d > 0 ? rsqrtf((float)d) : 0.0f;
    }
}

__global__ void scan_partial_kernel() {
    __shared__ int sh[256];
    int i = blockIdx.x * 256 + threadIdx.x;
    int v = (i < N_NODES) ? g_cnt_dst[i] : 0;
    sh[threadIdx.x] = v;
    __syncthreads();
    for (int s = 128; s > 0; s >>= 1) {
        if (threadIdx.x < s) sh[threadIdx.x] += sh[threadIdx.x + s];
        __syncthreads();
    }
    if (threadIdx.x == 0) g_partial[blockIdx.x] = sh[0];
}

__global__ void scan_offsets_kernel() {
    int acc = 0;
    for (int b = 0; b < NB_SCAN; b++) { int v = g_partial[b]; g_partial[b] = acc; acc += v; }
    g_rowptr[N_NODES] = N_EDGES;
}

__global__ void scan_final_kernel() {
    __shared__ int sh[256];
    int i = blockIdx.x * 256 + threadIdx.x;
    int v = (i < N_NODES) ? g_cnt_dst[i] : 0;
    sh[threadIdx.x] = v;
    __syncthreads();
    for (int s = 1; s < 256; s <<= 1) {
        int t = (threadIdx.x >= s) ? sh[threadIdx.x - s] : 0;
        __syncthreads();
        sh[threadIdx.x] += t;
        __syncthreads();
    }
    if (i < N_NODES) g_rowptr[i] = g_partial[blockIdx.x] + sh[threadIdx.x] - v;
}

__global__ void fill_kernel(const int* __restrict__ ei) {
    int i = blockIdx.x * blockDim.x + threadIdx.x;
    if (i < N_EDGES) {
        int s = ei[i], d = ei[N_EDGES + i];
        int pos = g_rowptr[d] + atomicAdd(&g_cursor[d], 1);
        float w = g_dinv[s] * g_dinv[d];
        g_csr[pos] = make_int2(s, __float_as_int(w));
    }
}

// ---------------- GEMM1 (tf32 tensor cores): g_h = relu(x @ W1 + b1) ----------------
#define SA_STRIDE 36
#define SB_STRIDE 264
#define A_SZ (64 * SA_STRIDE)
#define B_SZ (32 * SB_STRIDE)
#define GEMM1_SMEM (2 * (A_SZ + B_SZ) * 4)  /* 86016 bytes */

__device__ __forceinline__ unsigned int f2tf32(float f) {
    unsigned int r;
    asm volatile("cvt.rna.tf32.f32 %0, %1;" : "=r"(r) : "f"(f));
    return r;
}

__global__ void __launch_bounds__(256) gemm1_tc_kernel(
    const float* __restrict__ A, const float* __restrict__ W, const float* __restrict__ bias) {
    extern __shared__ float smem[];
    float* sAb[2] = { smem, smem + A_SZ + B_SZ };
    float* sBb[2] = { smem + A_SZ, smem + 2 * A_SZ + B_SZ };

    const int tid = threadIdx.x;
    const int m0 = blockIdx.x * 64;
    const int wid = tid >> 5, lane = tid & 31;
    const int warp_m = wid >> 2, warp_n = wid & 3;
    const int r = lane >> 2, c = lane & 3;

    float acc[2][8][4];
#pragma unroll
    for (int mt = 0; mt < 2; mt++)
#pragma unroll
        for (int nt = 0; nt < 8; nt++)
#pragma unroll
            for (int i = 0; i < 4; i++) acc[mt][nt][i] = 0.0f;

    auto load_tiles = [&](int buf, int k0) {
#pragma unroll
        for (int j = 0; j < 2; j++) {
            int idx = tid + j * 256;
            int row = idx >> 3, kv = (idx & 7) * 4;
            int gm = m0 + row, gk = k0 + kv;
            int v = (gm < N_NODES) && (gk < C_IN);
            const float* src = A + (size_t)(v ? gm : 0) * C_IN + (v ? gk : 0);
            unsigned int dst = (unsigned int)__cvta_generic_to_shared(sAb[buf] + row * SA_STRIDE + kv);
            int sz = v ? 16 : 0;
            asm volatile("cp.async.cg.shared.global [%0], [%1], 16, %2;\n"
                         :: "r"(dst), "l"(src), "r"(sz));
        }
#pragma unroll
        for (int j = 0; j < 8; j++) {
            int idx = tid + j * 256;
            int krow = idx >> 6, nv = (idx & 63) * 4;
            int gk = k0 + krow;
            int v = (gk < C_IN);
            const float* src = W + (size_t)(v ? gk : 0) * HIDDEN + nv;
            unsigned int dst = (unsigned int)__cvta_generic_to_shared(sBb[buf] + krow * SB_STRIDE + nv);
            int sz = v ? 16 : 0;
            asm volatile("cp.async.cg.shared.global [%0], [%1], 16, %2;\n"
                         :: "r"(dst), "l"(src), "r"(sz));
        }
        asm volatile("cp.async.commit_group;\n");
    };

    const int NIT = (C_IN + 31) / 32;
    load_tiles(0, 0);

    for (int it = 0; it < NIT; it++) {
        if (it + 1 < NIT) {
            load_tiles((it + 1) & 1, (it + 1) * 32);
            asm volatile("cp.async.wait_group 1;\n");
        } else {
            asm volatile("cp.async.wait_group 0;\n");
        }
        __syncthreads();

        const float* sA = sAb[it & 1];
        const float* sB = sBb[it & 1];

#pragma unroll
        for (int kk = 0; kk < 4; kk++) {
            const int kb = kk * 8;
            unsigned int af[2][4], bf[8][2];
#pragma unroll
            for (int mt = 0; mt < 2; mt++) {
                const float* base = sA + (warp_m * 32 + mt * 16 + r) * SA_STRIDE + kb + c;
                af[mt][0] = f2tf32(base[0]);
                af[mt][1] = f2tf32(base[8 * SA_STRIDE]);
                af[mt][2] = f2tf32(base[4]);
                af[mt][3] = f2tf32(base[8 * SA_STRIDE + 4]);
            }
#pragma unroll
            for (int nt = 0; nt < 8; nt++) {
                const float* base = sB + (kb + c) * SB_STRIDE + warp_n * 64 + nt * 8 + r;
                bf[nt][0] = f2tf32(base[0]);
                bf[nt][1] = f2tf32(base[4 * SB_STRIDE]);
            }
#pragma unroll
            for (int mt = 0; mt < 2; mt++)
#pragma unroll
                for (int nt = 0; nt < 8; nt++) {
                    asm volatile(
                        "mma.sync.aligned.m16n8k8.row.col.f32.tf32.tf32.f32 "
                        "{%0,%1,%2,%3}, {%4,%5,%6,%7}, {%8,%9}, {%0,%1,%2,%3};\n"
                        : "+f"(acc[mt][nt][0]), "+f"(acc[mt][nt][1]),
                          "+f"(acc[mt][nt][2]), "+f"(acc[mt][nt][3])
                        : "r"(af[mt][0]), "r"(af[mt][1]), "r"(af[mt][2]), "r"(af[mt][3]),
                          "r"(bf[nt][0]), "r"(bf[nt][1]));
                }
        }
        __syncthreads();
    }

#pragma unroll
    for (int mt = 0; mt < 2; mt++) {
#pragma unroll
        for (int nt = 0; nt < 8; nt++) {
            int gn = warp_n * 64 + nt * 8 + c * 2;
            float2 bv = *(const float2*)(bias + gn);
            int gm0 = m0 + warp_m * 32 + mt * 16 + r;
            if (gm0 < N_NODES) {
                float2 o;
                o.x = fmaxf(acc[mt][nt][0] + bv.x, 0.f);
                o.y = fmaxf(acc[mt][nt][1] + bv.y, 0.f);
                *(float2*)(g_h + (size_t)gm0 * HIDDEN + gn) = o;
            }
            int gm1 = gm0 + 8;
            if (gm1 < N_NODES) {
                float2 o;
                o.x = fmaxf(acc[mt][nt][2] + bv.x, 0.f);
                o.y = fmaxf(acc[mt][nt][3] + bv.y, 0.f);
                *(float2*)(g_h + (size_t)gm1 * HIDDEN + gn) = o;
            }
        }
    }
}

// ---------------- GEMM2: bufA(fp16) = g_h @ W2 + b2; hidden = temp[0]*v ----------------
__global__ void __launch_bounds__(256) gemm2_kernel(
    const float* __restrict__ W2, const float* __restrict__ b2, const float* __restrict__ temp) {
    __shared__ float shH[64 * 64];
    __shared__ float shW[64 * C_OUT];
    int tid = threadIdx.x;
    int r0 = blockIdx.x * 64;
    int lane = tid & 31, rg = tid >> 5;

    float acc0[8], acc1[8];
#pragma unroll
    for (int i = 0; i < 8; i++) { acc0[i] = 0.f; acc1[i] = 0.f; }

    for (int kc = 0; kc < HIDDEN; kc += 64) {
#pragma unroll
        for (int j = 0; j < 16; j++) {
            int idx = tid + j * 256;
            int r = idx >> 6, k = idx & 63;
            int gr = r0 + r;
            shH[idx] = (gr < N_NODES) ? g_h[(size_t)gr * HIDDEN + kc + k] : 0.f;
        }
        for (int idx = tid; idx < 64 * C_OUT; idx += 256) {
            int k = idx / C_OUT, cc = idx % C_OUT;
            shW[idx] = W2[(size_t)(kc + k) * C_OUT + cc];
        }
        __syncthreads();
#pragma unroll 4
        for (int k = 0; k < 64; k++) {
            float w0 = shW[k * C_OUT + lane];
            float w1 = (lane < C_OUT - 32) ? shW[k * C_OUT + lane + 32] : 0.f;
#pragma unroll
            for (int i = 0; i < 8; i++) {
                float a = shH[(rg * 8 + i) * 64 + k];
                acc0[i] += a * w0;
                acc1[i] += a * w1;
            }
        }
        __syncthreads();
    }

    float t0 = temp[0];
#pragma unroll
    for (int i = 0; i < 8; i++) {
        int r = r0 + rg * 8 + i;
        if (r >= N_NODES) continue;
        float v0 = acc0[i] + b2[lane];
        g_bufA[(size_t)r * C_PAD + lane] = __float2half_rn(v0);
        g_hidden[(size_t)r * C_OUT + lane] = t0 * v0;
        if (lane < C_OUT - 32) {
            float v1 = acc1[i] + b2[lane + 32];
            g_bufA[(size_t)r * C_PAD + lane + 32] = __float2half_rn(v1);
            g_hidden[(size_t)r * C_OUT + lane + 32] = t0 * v1;
        } else {
            // zero the padding columns 50..63 once; pull kernels keep them zero
            g_bufA[(size_t)r * C_PAD + lane + 32] = __float2half_rn(0.f);
        }
    }
}

// ---------------- pull hop 1: bufB[d] = sum w * bufA[src]  (fp16 rows, 1 line/edge) ----------------
__global__ void __launch_bounds__(256) pull1_kernel() {
    int node = (blockIdx.x * blockDim.x + threadIdx.x) >> 5;
    int lane = threadIdx.x & 31;
    if (node >= N_NODES) return;
    int beg = g_rowptr[node], end = g_rowptr[node + 1];
    float a0 = 0.f, a1 = 0.f;
    int e = beg;
    for (; e + 3 < end; e += 4) {
        int2 e0 = g_csr[e], e1 = g_csr[e + 1], e2 = g_csr[e + 2], e3 = g_csr[e + 3];
        half2 h0 = *(const half2*)(g_bufA + (size_t)e0.x * C_PAD + lane * 2);
        half2 h1 = *(const half2*)(g_bufA + (size_t)e1.x * C_PAD + lane * 2);
        half2 h2 = *(const half2*)(g_bufA + (size_t)e2.x * C_PAD + lane * 2);
        half2 h3 = *(const half2*)(g_bufA + (size_t)e3.x * C_PAD + lane * 2);
        float2 f0 = __half22float2(h0), f1 = __half22float2(h1);
        float2 f2 = __half22float2(h2), f3 = __half22float2(h3);
        float w0 = __int_as_float(e0.y), w1 = __int_as_float(e1.y);
        float w2 = __int_as_float(e2.y), w3 = __int_as_float(e3.y);
        a0 += w0 * f0.x + w1 * f1.x + w2 * f2.x + w3 * f3.x;
        a1 += w0 * f0.y + w1 * f1.y + w2 * f2.y + w3 * f3.y;
    }
    for (; e < end; e++) {
        int2 ed = g_csr[e];
        half2 hv = *(const half2*)(g_bufA + (size_t)ed.x * C_PAD + lane * 2);
        float2 fv = __half22float2(hv);
        float w = __int_as_float(ed.y);
        a0 += w * fv.x;
        a1 += w * fv.y;
    }
    *(half2*)(g_bufB + (size_t)node * C_PAD + lane * 2) = __floats2half2_rn(a0, a1);
}

// ---------------- pull hop 2 + axpy: bufA[d]=sum w*bufB[src]; hidden += t*val ----------------
__global__ void __launch_bounds__(256) pull2_kernel(const float* __restrict__ temp, int kidx) {
    int node = (blockIdx.x * blockDim.x + threadIdx.x) >> 5;
    int lane = threadIdx.x & 31;
    if (node >= N_NODES) return;
    float t = temp[kidx];
    int beg = g_rowptr[node], end = g_rowptr[node + 1];
    float a0 = 0.f, a1 = 0.f;
    int e = beg;
    for (; e + 3 < end; e += 4) {
        int2 e0 = g_csr[e], e1 = g_csr[e + 1], e2 = g_csr[e + 2], e3 = g_csr[e + 3];
        half2 h0 = *(const half2*)(g_bufB + (size_t)e0.x * C_PAD + lane * 2);
        half2 h1 = *(const half2*)(g_bufB + (size_t)e1.x * C_PAD + lane * 2);
        half2 h2 = *(const half2*)(g_bufB + (size_t)e2.x * C_PAD + lane * 2);
        half2 h3 = *(const half2*)(g_bufB + (size_t)e3.x * C_PAD + lane * 2);
        float2 f0 = __half22float2(h0), f1 = __half22float2(h1);
        float2 f2 = __half22float2(h2), f3 = __half22float2(h3);
        float w0 = __int_as_float(e0.y), w1 = __int_as_float(e1.y);
        float w2 = __int_as_float(e2.y), w3 = __int_as_float(e3.y);
        a0 += w0 * f0.x + w1 * f1.x + w2 * f2.x + w3 * f3.x;
        a1 += w0 * f0.y + w1 * f1.y + w2 * f2.y + w3 * f3.y;
    }
    for (; e < end; e++) {
        int2 ed = g_csr[e];
        half2 hv = *(const half2*)(g_bufB + (size_t)ed.x * C_PAD + lane * 2);
        float2 fv = __half22float2(hv);
        float w = __int_as_float(ed.y);
        a0 += w * fv.x;
        a1 += w * fv.y;
    }
    *(half2*)(g_bufA + (size_t)node * C_PAD + lane * 2) = __floats2half2_rn(a0, a1);
    // fp32 accumulation into hidden (cols 2*lane, 2*lane+1 valid for lane<25)
    if (lane < C_OUT / 2) {
        float* hrow = g_hidden + (size_t)node * C_OUT + lane * 2;
        hrow[0] += t * a0;
        hrow[1] += t * a1;
    }
}

// ---------------- log_softmax over rows of 50 ----------------
__global__ void __launch_bounds__(256) logsoftmax_kernel(float* __restrict__ out) {
    int node = (blockIdx.x * blockDim.x + threadIdx.x) >> 5;
    int lane = threadIdx.x & 31;
    if (node >= N_NODES) return;
    const float* row = g_hidden + (size_t)node * C_OUT;
    float v0 = row[lane];
    float v1 = (lane < C_OUT - 32) ? row[lane + 32] : -INFINITY;
    float m = fmaxf(v0, v1);
#pragma unroll
    for (int o = 16; o > 0; o >>= 1) m = fmaxf(m, __shfl_xor_sync(0xffffffffu, m, o));
    float s = expf(v0 - m) + ((lane < C_OUT - 32) ? expf(v1 - m) : 0.f);
#pragma unroll
    for (int o = 16; o > 0; o >>= 1) s += __shfl_xor_sync(0xffffffffu, s, o);
    float l = m + logf(s);
    float* orow = out + (size_t)node * C_OUT;
    orow[lane] = v0 - l;
    if (lane < C_OUT - 32) orow[lane + 32] = v1 - l;
}

// ---------------- launch ----------------
extern "C" void kernel_launch(void* const* d_in, const int* in_sizes, int n_in,
                              void* d_out, int out_size) {
    const float* x    = (const float*)d_in[0];
    const int*   ei   = (const int*)d_in[1];
    const float* W1   = (const float*)d_in[2];
    const float* b1   = (const float*)d_in[3];
    const float* W2   = (const float*)d_in[4];
    const float* b2   = (const float*)d_in[5];
    const float* temp = (const float*)d_in[6];
    float* out = (float*)d_out;

    int nb_nodes = (N_NODES + 255) / 256;
    int nb_edges = (N_EDGES + 255) / 256;

    zero_kernel<<<nb_nodes, 256>>>();
    count_kernel<<<nb_edges, 256>>>(ei);
    dinv_kernel<<<nb_nodes, 256>>>();
    scan_partial_kernel<<<NB_SCAN, 256>>>();
    scan_offsets_kernel<<<1, 1>>>();
    scan_final_kernel<<<NB_SCAN, 256>>>();
    fill_kernel<<<nb_edges, 256>>>(ei);

    static int smem_set = 0;
    if (!smem_set) {
        cudaFuncSetAttribute(gemm1_tc_kernel, cudaFuncAttributeMaxDynamicSharedMemorySize, GEMM1_SMEM);
        smem_set = 1;
    }
    gemm1_tc_kernel<<<(N_NODES + 63) / 64, 256, GEMM1_SMEM>>>(x, W1, b1);
    gemm2_kernel<<<(N_NODES + 63) / 64, 256>>>(W2, b2, temp);

    int pull_grid = (N_NODES * 32 + 255) / 256;
    for (int k = 0; k < K_HALF; k++) {
        pull1_kernel<<<pull_grid, 256>>>();
        pull2_kernel<<<pull_grid, 256>>>(temp, k + 1);
    }

    logsoftmax_kernel<<<pull_grid, 256>>>(out);
}

// round 5
// speedup vs baseline: 1.8725x; 1.0530x over previous
#include <cuda_runtime.h>
#include <cuda_fp16.h>
#include <cstdint>
#include <math.h>

#define N_NODES 100000
#define N_EDGES 1600000
#define C_IN 500
#define HIDDEN 256
#define C_OUT 50
#define C_PAD 64            /* padded fp16 row: 64 halves = 128 bytes, line-aligned */
#define K_HALF 5
#define NB_SCAN 391  /* ceil(100000/256) */

// ---------------- scratch (static device globals; no allocation) ----------------
__device__ float  g_h[25600000];           // [N, HIDDEN]
__device__ __half g_bufA[N_NODES * C_PAD]; // [N, 64] fp16 padded
__device__ __half g_bufB[N_NODES * C_PAD]; // [N, 64] fp16 padded
__device__ float  g_hidden[5000000];       // [N, C_OUT] fp32 accumulator
__device__ float  g_dinv[N_NODES];
__device__ int    g_cnt_src[N_NODES];
__device__ int    g_cnt_dst[N_NODES];
__device__ int    g_cursor[N_NODES];
__device__ int    g_rowptr[N_NODES + 1];
__device__ int2   g_csr[N_EDGES];          // (src, w as float bits)
__device__ int    g_partial[512];

// ---------------- graph preprocessing ----------------
__global__ void zero_kernel() {
    int i = blockIdx.x * blockDim.x + threadIdx.x;
    if (i < N_NODES) { g_cnt_src[i] = 0; g_cnt_dst[i] = 0; g_cursor[i] = 0; }
}

__global__ void count_kernel(const int* __restrict__ ei) {
    int i = blockIdx.x * blockDim.x + threadIdx.x;
    if (i < N_EDGES) {
        atomicAdd(&g_cnt_src[ei[i]], 1);
        atomicAdd(&g_cnt_dst[ei[N_EDGES + i]], 1);
    }
}

__global__ void dinv_kernel() {
    int i = blockIdx.x * blockDim.x + threadIdx.x;
    if (i < N_NODES) {
        int d = g_cnt_src[i];
        g_dinv[i] = d > 0 ? rsqrtf((float)d) : 0.0f;
    }
}

__global__ void scan_partial_kernel() {
    __shared__ int sh[256];
    int i = blockIdx.x * 256 + threadIdx.x;
    int v = (i < N_NODES) ? g_cnt_dst[i] : 0;
    sh[threadIdx.x] = v;
    __syncthreads();
    for (int s = 128; s > 0; s >>= 1) {
        if (threadIdx.x < s) sh[threadIdx.x] += sh[threadIdx.x + s];
        __syncthreads();
    }
    if (threadIdx.x == 0) g_partial[blockIdx.x] = sh[0];
}

__global__ void scan_offsets_kernel() {
    int acc = 0;
    for (int b = 0; b < NB_SCAN; b++) { int v = g_partial[b]; g_partial[b] = acc; acc += v; }
    g_rowptr[N_NODES] = N_EDGES;
}

__global__ void scan_final_kernel() {
    __shared__ int sh[256];
    int i = blockIdx.x * 256 + threadIdx.x;
    int v = (i < N_NODES) ? g_cnt_dst[i] : 0;
    sh[threadIdx.x] = v;
    __syncthreads();
    for (int s = 1; s < 256; s <<= 1) {
        int t = (threadIdx.x >= s) ? sh[threadIdx.x - s] : 0;
        __syncthreads();
        sh[threadIdx.x] += t;
        __syncthreads();
    }
    if (i < N_NODES) g_rowptr[i] = g_partial[blockIdx.x] + sh[threadIdx.x] - v;
}

__global__ void fill_kernel(const int* __restrict__ ei) {
    int i = blockIdx.x * blockDim.x + threadIdx.x;
    if (i < N_EDGES) {
        int s = ei[i], d = ei[N_EDGES + i];
        int pos = g_rowptr[d] + atomicAdd(&g_cursor[d], 1);
        float w = g_dinv[s] * g_dinv[d];
        g_csr[pos] = make_int2(s, __float_as_int(w));
    }
}

// ---------------- GEMM1 (tf32 tensor cores): g_h = relu(x @ W1 + b1) ----------------
// fp32 values passed straight to tf32 mma (HW ignores low 13 mantissa bits).
#define SA_STRIDE 36
#define SB_STRIDE 264
#define A_SZ (64 * SA_STRIDE)
#define B_SZ (32 * SB_STRIDE)
#define GEMM1_SMEM (2 * (A_SZ + B_SZ) * 4)  /* 86016 bytes */

__global__ void __launch_bounds__(256) gemm1_tc_kernel(
    const float* __restrict__ A, const float* __restrict__ W, const float* __restrict__ bias) {
    extern __shared__ float smem[];
    float* sAb[2] = { smem, smem + A_SZ + B_SZ };
    float* sBb[2] = { smem + A_SZ, smem + 2 * A_SZ + B_SZ };

    const int tid = threadIdx.x;
    const int m0 = blockIdx.x * 64;
    const int wid = tid >> 5, lane = tid & 31;
    const int warp_m = wid >> 2, warp_n = wid & 3;
    const int r = lane >> 2, c = lane & 3;

    float acc[2][8][4];
#pragma unroll
    for (int mt = 0; mt < 2; mt++)
#pragma unroll
        for (int nt = 0; nt < 8; nt++)
#pragma unroll
            for (int i = 0; i < 4; i++) acc[mt][nt][i] = 0.0f;

    auto load_tiles = [&](int buf, int k0) {
#pragma unroll
        for (int j = 0; j < 2; j++) {
            int idx = tid + j * 256;
            int row = idx >> 3, kv = (idx & 7) * 4;
            int gm = m0 + row, gk = k0 + kv;
            int v = (gm < N_NODES) && (gk < C_IN);
            const float* src = A + (size_t)(v ? gm : 0) * C_IN + (v ? gk : 0);
            unsigned int dst = (unsigned int)__cvta_generic_to_shared(sAb[buf] + row * SA_STRIDE + kv);
            int sz = v ? 16 : 0;
            asm volatile("cp.async.cg.shared.global [%0], [%1], 16, %2;\n"
                         :: "r"(dst), "l"(src), "r"(sz));
        }
#pragma unroll
        for (int j = 0; j < 8; j++) {
            int idx = tid + j * 256;
            int krow = idx >> 6, nv = (idx & 63) * 4;
            int gk = k0 + krow;
            int v = (gk < C_IN);
            const float* src = W + (size_t)(v ? gk : 0) * HIDDEN + nv;
            unsigned int dst = (unsigned int)__cvta_generic_to_shared(sBb[buf] + krow * SB_STRIDE + nv);
            int sz = v ? 16 : 0;
            asm volatile("cp.async.cg.shared.global [%0], [%1], 16, %2;\n"
                         :: "r"(dst), "l"(src), "r"(sz));
        }
        asm volatile("cp.async.commit_group;\n");
    };

    const int NIT = (C_IN + 31) / 32;
    load_tiles(0, 0);

    for (int it = 0; it < NIT; it++) {
        if (it + 1 < NIT) {
            load_tiles((it + 1) & 1, (it + 1) * 32);
            asm volatile("cp.async.wait_group 1;\n");
        } else {
            asm volatile("cp.async.wait_group 0;\n");
        }
        __syncthreads();

        const float* sA = sAb[it & 1];
        const float* sB = sBb[it & 1];

#pragma unroll
        for (int kk = 0; kk < 4; kk++) {
            const int kb = kk * 8;
            unsigned int af[2][4], bf[8][2];
#pragma unroll
            for (int mt = 0; mt < 2; mt++) {
                const unsigned int* base = (const unsigned int*)(sA + (warp_m * 32 + mt * 16 + r) * SA_STRIDE + kb + c);
                af[mt][0] = base[0];
                af[mt][1] = base[8 * SA_STRIDE];
                af[mt][2] = base[4];
                af[mt][3] = base[8 * SA_STRIDE + 4];
            }
#pragma unroll
            for (int nt = 0; nt < 8; nt++) {
                const unsigned int* base = (const unsigned int*)(sB + (kb + c) * SB_STRIDE + warp_n * 64 + nt * 8 + r);
                bf[nt][0] = base[0];
                bf[nt][1] = base[4 * SB_STRIDE];
            }
#pragma unroll
            for (int mt = 0; mt < 2; mt++)
#pragma unroll
                for (int nt = 0; nt < 8; nt++) {
                    asm volatile(
                        "mma.sync.aligned.m16n8k8.row.col.f32.tf32.tf32.f32 "
                        "{%0,%1,%2,%3}, {%4,%5,%6,%7}, {%8,%9}, {%0,%1,%2,%3};\n"
                        : "+f"(acc[mt][nt][0]), "+f"(acc[mt][nt][1]),
                          "+f"(acc[mt][nt][2]), "+f"(acc[mt][nt][3])
                        : "r"(af[mt][0]), "r"(af[mt][1]), "r"(af[mt][2]), "r"(af[mt][3]),
                          "r"(bf[nt][0]), "r"(bf[nt][1]));
                }
        }
        __syncthreads();
    }

#pragma unroll
    for (int mt = 0; mt < 2; mt++) {
#pragma unroll
        for (int nt = 0; nt < 8; nt++) {
            int gn = warp_n * 64 + nt * 8 + c * 2;
            float2 bv = *(const float2*)(bias + gn);
            int gm0 = m0 + warp_m * 32 + mt * 16 + r;
            if (gm0 < N_NODES) {
                float2 o;
                o.x = fmaxf(acc[mt][nt][0] + bv.x, 0.f);
                o.y = fmaxf(acc[mt][nt][1] + bv.y, 0.f);
                *(float2*)(g_h + (size_t)gm0 * HIDDEN + gn) = o;
            }
            int gm1 = gm0 + 8;
            if (gm1 < N_NODES) {
                float2 o;
                o.x = fmaxf(acc[mt][nt][2] + bv.x, 0.f);
                o.y = fmaxf(acc[mt][nt][3] + bv.y, 0.f);
                *(float2*)(g_h + (size_t)gm1 * HIDDEN + gn) = o;
            }
        }
    }
}

// ---------------- GEMM2: bufA(fp16) = g_h @ W2 + b2; hidden = temp[0]*v ----------------
__global__ void __launch_bounds__(256) gemm2_kernel(
    const float* __restrict__ W2, const float* __restrict__ b2, const float* __restrict__ temp) {
    __shared__ float shH[64 * 64];
    __shared__ float shW[64 * C_OUT];
    int tid = threadIdx.x;
    int r0 = blockIdx.x * 64;
    int lane = tid & 31, rg = tid >> 5;

    float acc0[8], acc1[8];
#pragma unroll
    for (int i = 0; i < 8; i++) { acc0[i] = 0.f; acc1[i] = 0.f; }

    for (int kc = 0; kc < HIDDEN; kc += 64) {
#pragma unroll
        for (int j = 0; j < 16; j++) {
            int idx = tid + j * 256;
            int r = idx >> 6, k = idx & 63;
            int gr = r0 + r;
            shH[idx] = (gr < N_NODES) ? g_h[(size_t)gr * HIDDEN + kc + k] : 0.f;
        }
        for (int idx = tid; idx < 64 * C_OUT; idx += 256) {
            int k = idx / C_OUT, cc = idx % C_OUT;
            shW[idx] = W2[(size_t)(kc + k) * C_OUT + cc];
        }
        __syncthreads();
#pragma unroll 4
        for (int k = 0; k < 64; k++) {
            float w0 = shW[k * C_OUT + lane];
            float w1 = (lane < C_OUT - 32) ? shW[k * C_OUT + lane + 32] : 0.f;
#pragma unroll
            for (int i = 0; i < 8; i++) {
                float a = shH[(rg * 8 + i) * 64 + k];
                acc0[i] += a * w0;
                acc1[i] += a * w1;
            }
        }
        __syncthreads();
    }

    float t0 = temp[0];
#pragma unroll
    for (int i = 0; i < 8; i++) {
        int r = r0 + rg * 8 + i;
        if (r >= N_NODES) continue;
        float v0 = acc0[i] + b2[lane];
        g_bufA[(size_t)r * C_PAD + lane] = __float2half_rn(v0);
        g_hidden[(size_t)r * C_OUT + lane] = t0 * v0;
        if (lane < C_OUT - 32) {
            float v1 = acc1[i] + b2[lane + 32];
            g_bufA[(size_t)r * C_PAD + lane + 32] = __float2half_rn(v1);
            g_hidden[(size_t)r * C_OUT + lane + 32] = t0 * v1;
        } else {
            g_bufA[(size_t)r * C_PAD + lane + 32] = __float2half_rn(0.f);
        }
    }
}

// ---------------- pull hop 1: bufB[d] = sum w * bufA[src]  (fp16 rows, 1 line/edge) ----------------
__global__ void __launch_bounds__(256) pull1_kernel() {
    int node = (blockIdx.x * blockDim.x + threadIdx.x) >> 5;
    int lane = threadIdx.x & 31;
    if (node >= N_NODES) return;
    int beg = g_rowptr[node], end = g_rowptr[node + 1];
    float a0 = 0.f, a1 = 0.f;
    int e = beg;
    for (; e + 3 < end; e += 4) {
        int2 e0 = g_csr[e], e1 = g_csr[e + 1], e2 = g_csr[e + 2], e3 = g_csr[e + 3];
        half2 h0 = *(const half2*)(g_bufA + (size_t)e0.x * C_PAD + lane * 2);
        half2 h1 = *(const half2*)(g_bufA + (size_t)e1.x * C_PAD + lane * 2);
        half2 h2 = *(const half2*)(g_bufA + (size_t)e2.x * C_PAD + lane * 2);
        half2 h3 = *(const half2*)(g_bufA + (size_t)e3.x * C_PAD + lane * 2);
        float2 f0 = __half22float2(h0), f1 = __half22float2(h1);
        float2 f2 = __half22float2(h2), f3 = __half22float2(h3);
        float w0 = __int_as_float(e0.y), w1 = __int_as_float(e1.y);
        float w2 = __int_as_float(e2.y), w3 = __int_as_float(e3.y);
        a0 += w0 * f0.x + w1 * f1.x + w2 * f2.x + w3 * f3.x;
        a1 += w0 * f0.y + w1 * f1.y + w2 * f2.y + w3 * f3.y;
    }
    for (; e < end; e++) {
        int2 ed = g_csr[e];
        half2 hv = *(const half2*)(g_bufA + (size_t)ed.x * C_PAD + lane * 2);
        float2 fv = __half22float2(hv);
        float w = __int_as_float(ed.y);
        a0 += w * fv.x;
        a1 += w * fv.y;
    }
    *(half2*)(g_bufB + (size_t)node * C_PAD + lane * 2) = __floats2half2_rn(a0, a1);
}

// ---------------- pull hop 2 + axpy: bufA[d]=sum w*bufB[src]; hidden += t*val ----------------
__global__ void __launch_bounds__(256) pull2_kernel(const float* __restrict__ temp, int kidx) {
    int node = (blockIdx.x * blockDim.x + threadIdx.x) >> 5;
    int lane = threadIdx.x & 31;
    if (node >= N_NODES) return;
    float t = temp[kidx];
    int beg = g_rowptr[node], end = g_rowptr[node + 1];
    float a0 = 0.f, a1 = 0.f;
    int e = beg;
    for (; e + 3 < end; e += 4) {
        int2 e0 = g_csr[e], e1 = g_csr[e + 1], e2 = g_csr[e + 2], e3 = g_csr[e + 3];
        half2 h0 = *(const half2*)(g_bufB + (size_t)e0.x * C_PAD + lane * 2);
        half2 h1 = *(const half2*)(g_bufB + (size_t)e1.x * C_PAD + lane * 2);
        half2 h2 = *(const half2*)(g_bufB + (size_t)e2.x * C_PAD + lane * 2);
        half2 h3 = *(const half2*)(g_bufB + (size_t)e3.x * C_PAD + lane * 2);
        float2 f0 = __half22float2(h0), f1 = __half22float2(h1);
        float2 f2 = __half22float2(h2), f3 = __half22float2(h3);
        float w0 = __int_as_float(e0.y), w1 = __int_as_float(e1.y);
        float w2 = __int_as_float(e2.y), w3 = __int_as_float(e3.y);
        a0 += w0 * f0.x + w1 * f1.x + w2 * f2.x + w3 * f3.x;
        a1 += w0 * f0.y + w1 * f1.y + w2 * f2.y + w3 * f3.y;
    }
    for (; e < end; e++) {
        int2 ed = g_csr[e];
        half2 hv = *(const half2*)(g_bufB + (size_t)ed.x * C_PAD + lane * 2);
        float2 fv = __half22float2(hv);
        float w = __int_as_float(ed.y);
        a0 += w * fv.x;
        a1 += w * fv.y;
    }
    *(half2*)(g_bufA + (size_t)node * C_PAD + lane * 2) = __floats2half2_rn(a0, a1);
    if (lane < C_OUT / 2) {
        float* hrow = g_hidden + (size_t)node * C_OUT + lane * 2;
        hrow[0] += t * a0;
        hrow[1] += t * a1;
    }
}

// ---------------- log_softmax over rows of 50 ----------------
__global__ void __launch_bounds__(256) logsoftmax_kernel(float* __restrict__ out) {
    int node = (blockIdx.x * blockDim.x + threadIdx.x) >> 5;
    int lane = threadIdx.x & 31;
    if (node >= N_NODES) return;
    const float* row = g_hidden + (size_t)node * C_OUT;
    float v0 = row[lane];
    float v1 = (lane < C_OUT - 32) ? row[lane + 32] : -INFINITY;
    float m = fmaxf(v0, v1);
#pragma unroll
    for (int o = 16; o > 0; o >>= 1) m = fmaxf(m, __shfl_xor_sync(0xffffffffu, m, o));
    float s = expf(v0 - m) + ((lane < C_OUT - 32) ? expf(v1 - m) : 0.f);
#pragma unroll
    for (int o = 16; o > 0; o >>= 1) s += __shfl_xor_sync(0xffffffffu, s, o);
    float l = m + logf(s);
    float* orow = out + (size_t)node * C_OUT;
    orow[lane] = v0 - l;
    if (lane < C_OUT - 32) orow[lane + 32] = v1 - l;
}

// ---------------- launch ----------------
extern "C" void kernel_launch(void* const* d_in, const int* in_sizes, int n_in,
                              void* d_out, int out_size) {
    const float* x    = (const float*)d_in[0];
    const int*   ei   = (const int*)d_in[1];
    const float* W1   = (const float*)d_in[2];
    const float* b1   = (const float*)d_in[3];
    const float* W2   = (const float*)d_in[4];
    const float* b2   = (const float*)d_in[5];
    const float* temp = (const float*)d_in[6];
    float* out = (float*)d_out;

    int nb_nodes = (N_NODES + 255) / 256;
    int nb_edges = (N_EDGES + 255) / 256;

    static int smem_set = 0;
    if (!smem_set) {
        cudaFuncSetAttribute(gemm1_tc_kernel, cudaFuncAttributeMaxDynamicSharedMemorySize, GEMM1_SMEM);
        smem_set = 1;
    }

    // Launch order places gemm1 at my index 3 = ncu's captured slot (s=5 with 2 harness launches ahead).
    zero_kernel<<<nb_nodes, 256>>>();                         // 0
    count_kernel<<<nb_edges, 256>>>(ei);                      // 1
    dinv_kernel<<<nb_nodes, 256>>>();                         // 2
    gemm1_tc_kernel<<<(N_NODES + 63) / 64, 256, GEMM1_SMEM>>>(x, W1, b1);  // 3 <- profiled
    scan_partial_kernel<<<NB_SCAN, 256>>>();                  // 4
    scan_offsets_kernel<<<1, 1>>>();                          // 5
    scan_final_kernel<<<NB_SCAN, 256>>>();                    // 6
    fill_kernel<<<nb_edges, 256>>>(ei);                       // 7
    gemm2_kernel<<<(N_NODES + 63) / 64, 256>>>(W2, b2, temp); // 8

    int pull_grid = (N_NODES * 32 + 255) / 256;
    for (int k = 0; k < K_HALF; k++) {
        pull1_kernel<<<pull_grid, 256>>>();
        pull2_kernel<<<pull_grid, 256>>>(temp, k + 1);
    }

    logsoftmax_kernel<<<pull_grid, 256>>>(out);
}

// round 7
// speedup vs baseline: 1.9415x; 1.0368x over previous
#include <cuda_runtime.h>
#include <cuda_fp16.h>
#include <cstdint>
#include <math.h>

#define N_NODES 100000
#define N_EDGES 1600000
#define C_IN 500
#define HIDDEN 256
#define C_OUT 50
#define C_PAD 64
#define K_HALF 5
#define NB_SCAN 391

// ---------------- scratch (static device globals; no allocation) ----------------
__device__ float  g_h[25600000];           // [N, HIDDEN]
__device__ __half g_bufA[N_NODES * C_PAD];
__device__ __half g_bufB[N_NODES * C_PAD];
__device__ float  g_hidden[5000000];
__device__ float  g_dinv[N_NODES];
__device__ int    g_cnt_src[N_NODES];
__device__ int    g_cnt_dst[N_NODES];
__device__ int    g_cursor[N_NODES];
__device__ int    g_rowptr[N_NODES + 1];
__device__ int2   g_csr[N_EDGES];
__device__ int    g_partial[512];

// ---------------- graph preprocessing ----------------
__global__ void zero_kernel() {
    int i = blockIdx.x * blockDim.x + threadIdx.x;
    if (i < N_NODES) { g_cnt_src[i] = 0; g_cnt_dst[i] = 0; g_cursor[i] = 0; }
}

__global__ void count_kernel(const int* __restrict__ ei) {
    int i = blockIdx.x * blockDim.x + threadIdx.x;
    if (i < N_EDGES) {
        atomicAdd(&g_cnt_src[ei[i]], 1);
        atomicAdd(&g_cnt_dst[ei[N_EDGES + i]], 1);
    }
}

__global__ void dinv_kernel() {
    int i = blockIdx.x * blockDim.x + threadIdx.x;
    if (i < N_NODES) {
        int d = g_cnt_src[i];
        g_dinv[i] = d > 0 ? rsqrtf((float)d) : 0.0f;
    }
}

__global__ void scan_partial_kernel() {
    __shared__ int sh[256];
    int i = blockIdx.x * 256 + threadIdx.x;
    int v = (i < N_NODES) ? g_cnt_dst[i] : 0;
    sh[threadIdx.x] = v;
    __syncthreads();
    for (int s = 128; s > 0; s >>= 1) {
        if (threadIdx.x < s) sh[threadIdx.x] += sh[threadIdx.x + s];
        __syncthreads();
    }
    if (threadIdx.x == 0) g_partial[blockIdx.x] = sh[0];
}

__global__ void scan_offsets_kernel() {
    int acc = 0;
    for (int b = 0; b < NB_SCAN; b++) { int v = g_partial[b]; g_partial[b] = acc; acc += v; }
    g_rowptr[N_NODES] = N_EDGES;
}

__global__ void scan_final_kernel() {
    __shared__ int sh[256];
    int i = blockIdx.x * 256 + threadIdx.x;
    int v = (i < N_NODES) ? g_cnt_dst[i] : 0;
    sh[threadIdx.x] = v;
    __syncthreads();
    for (int s = 1; s < 256; s <<= 1) {
        int t = (threadIdx.x >= s) ? sh[threadIdx.x - s] : 0;
        __syncthreads();
        sh[threadIdx.x] += t;
        __syncthreads();
    }
    if (i < N_NODES) g_rowptr[i] = g_partial[blockIdx.x] + sh[threadIdx.x] - v;
}

__global__ void fill_kernel(const int* __restrict__ ei) {
    int i = blockIdx.x * blockDim.x + threadIdx.x;
    if (i < N_EDGES) {
        int s = ei[i], d = ei[N_EDGES + i];
        int pos = g_rowptr[d] + atomicAdd(&g_cursor[d], 1);
        float w = g_dinv[s] * g_dinv[d];
        g_csr[pos] = make_int2(s, __float_as_int(w));
    }
}

// ---------------- GEMM1 (tf32 mma.sync): g_h = relu(x @ W1 + b1) ----------------
#define SA_STRIDE 36
#define SB_STRIDE 264
#define A_SZ (64 * SA_STRIDE)
#define B_SZ (32 * SB_STRIDE)
#define GEMM1_SMEM (2 * (A_SZ + B_SZ) * 4)  /* 86016 bytes */

__global__ void __launch_bounds__(256) gemm1_tc_kernel(
    const float* __restrict__ A, const float* __restrict__ W, const float* __restrict__ bias) {
    extern __shared__ float smem[];
    float* sAb[2] = { smem, smem + A_SZ + B_SZ };
    float* sBb[2] = { smem + A_SZ, smem + 2 * A_SZ + B_SZ };

    const int tid = threadIdx.x;
    const int m0 = blockIdx.x * 64;
    const int wid = tid >> 5, lane = tid & 31;
    const int warp_m = wid >> 2, warp_n = wid & 3;
    const int r = lane >> 2, c = lane & 3;

    float acc[2][8][4];
#pragma unroll
    for (int mt = 0; mt < 2; mt++)
#pragma unroll
        for (int nt = 0; nt < 8; nt++)
#pragma unroll
            for (int i = 0; i < 4; i++) acc[mt][nt][i] = 0.0f;

    auto load_tiles = [&](int buf, int k0) {
#pragma unroll
        for (int j = 0; j < 2; j++) {
            int idx = tid + j * 256;
            int row = idx >> 3, kv = (idx & 7) * 4;
            int gm = m0 + row, gk = k0 + kv;
            int v = (gm < N_NODES) && (gk < C_IN);
            const float* src = A + (size_t)(v ? gm : 0) * C_IN + (v ? gk : 0);
            unsigned int dst = (unsigned int)__cvta_generic_to_shared(sAb[buf] + row * SA_STRIDE + kv);
            int sz = v ? 16 : 0;
            asm volatile("cp.async.cg.shared.global [%0], [%1], 16, %2;\n"
                         :: "r"(dst), "l"(src), "r"(sz));
        }
#pragma unroll
        for (int j = 0; j < 8; j++) {
            int idx = tid + j * 256;
            int krow = idx >> 6, nv = (idx & 63) * 4;
            int gk = k0 + krow;
            int v = (gk < C_IN);
            const float* src = W + (size_t)(v ? gk : 0) * HIDDEN + nv;
            unsigned int dst = (unsigned int)__cvta_generic_to_shared(sBb[buf] + krow * SB_STRIDE + nv);
            int sz = v ? 16 : 0;
            asm volatile("cp.async.cg.shared.global [%0], [%1], 16, %2;\n"
                         :: "r"(dst), "l"(src), "r"(sz));
        }
        asm volatile("cp.async.commit_group;\n");
    };

    const int NIT = (C_IN + 31) / 32;
    load_tiles(0, 0);

    for (int it = 0; it < NIT; it++) {
        if (it + 1 < NIT) {
            load_tiles((it + 1) & 1, (it + 1) * 32);
            asm volatile("cp.async.wait_group 1;\n");
        } else {
            asm volatile("cp.async.wait_group 0;\n");
        }
        __syncthreads();

        const float* sA = sAb[it & 1];
        const float* sB = sBb[it & 1];

#pragma unroll
        for (int kk = 0; kk < 4; kk++) {
            const int kb = kk * 8;
            unsigned int af[2][4], bf[8][2];
#pragma unroll
            for (int mt = 0; mt < 2; mt++) {
                const unsigned int* base = (const unsigned int*)(sA + (warp_m * 32 + mt * 16 + r) * SA_STRIDE + kb + c);
                af[mt][0] = base[0];
                af[mt][1] = base[8 * SA_STRIDE];
                af[mt][2] = base[4];
                af[mt][3] = base[8 * SA_STRIDE + 4];
            }
#pragma unroll
            for (int nt = 0; nt < 8; nt++) {
                const unsigned int* base = (const unsigned int*)(sB + (kb + c) * SB_STRIDE + warp_n * 64 + nt * 8 + r);
                bf[nt][0] = base[0];
                bf[nt][1] = base[4 * SB_STRIDE];
            }
#pragma unroll
            for (int mt = 0; mt < 2; mt++)
#pragma unroll
                for (int nt = 0; nt < 8; nt++) {
                    asm volatile(
                        "mma.sync.aligned.m16n8k8.row.col.f32.tf32.tf32.f32 "
                        "{%0,%1,%2,%3}, {%4,%5,%6,%7}, {%8,%9}, {%0,%1,%2,%3};\n"
                        : "+f"(acc[mt][nt][0]), "+f"(acc[mt][nt][1]),
                          "+f"(acc[mt][nt][2]), "+f"(acc[mt][nt][3])
                        : "r"(af[mt][0]), "r"(af[mt][1]), "r"(af[mt][2]), "r"(af[mt][3]),
                          "r"(bf[nt][0]), "r"(bf[nt][1]));
                }
        }
        __syncthreads();
    }

#pragma unroll
    for (int mt = 0; mt < 2; mt++) {
#pragma unroll
        for (int nt = 0; nt < 8; nt++) {
            int gn = warp_n * 64 + nt * 8 + c * 2;
            float2 bv = *(const float2*)(bias + gn);
            int gm0 = m0 + warp_m * 32 + mt * 16 + r;
            if (gm0 < N_NODES) {
                float2 o;
                o.x = fmaxf(acc[mt][nt][0] + bv.x, 0.f);
                o.y = fmaxf(acc[mt][nt][1] + bv.y, 0.f);
                *(float2*)(g_h + (size_t)gm0 * HIDDEN + gn) = o;
            }
            int gm1 = gm0 + 8;
            if (gm1 < N_NODES) {
                float2 o;
                o.x = fmaxf(acc[mt][nt][2] + bv.x, 0.f);
                o.y = fmaxf(acc[mt][nt][3] + bv.y, 0.f);
                *(float2*)(g_h + (size_t)gm1 * HIDDEN + gn) = o;
            }
        }
    }
}

// ---------------- GEMM2 (tf32 mma.sync): bufA(fp16)=g_h@W2+b2; hidden=temp[0]*v ----------------
// BM=128/CTA, N=64 (50 padded), K=256. W2 staged whole in smem [k][n] stride 72.
// A tiles (g_h) double-buffered cp.async, stride 36.
#define G2_SW_ST 72
#define G2_SW_BYTES (256 * G2_SW_ST * 4)      /* 73728 */
#define G2_SA_BYTES (128 * SA_STRIDE * 4)     /* 18432 */
#define G2_SMEM (G2_SW_BYTES + 2 * G2_SA_BYTES)  /* 110592 */

__global__ void __launch_bounds__(128) gemm2_tc_kernel(
    const float* __restrict__ W2, const float* __restrict__ b2, const float* __restrict__ temp) {
    extern __shared__ float smem[];
    float* sW = smem;                               // [256][72]
    float* sAb[2] = { smem + G2_SW_BYTES / 4, smem + G2_SW_BYTES / 4 + G2_SA_BYTES / 4 };

    const int tid = threadIdx.x;
    const int m0 = blockIdx.x * 128;
    const int wid = tid >> 5, lane = tid & 31;
    const int r = lane >> 2, c = lane & 3;

    // stage W2 -> smem [k][n], zero-pad n>=50
    for (int idx = tid; idx < 256 * 64; idx += 128) {
        int k = idx >> 6, n = idx & 63;
        sW[k * G2_SW_ST + n] = (n < C_OUT) ? __ldg(W2 + (size_t)k * C_OUT + n) : 0.f;
    }

    auto load_a = [&](int t) {
        float* dstb = sAb[t & 1];
        int k0 = t * 32;
#pragma unroll
        for (int j = 0; j < 8; j++) {
            int idx = tid + j * 128;
            int row = idx >> 3, kv = (idx & 7) * 4;
            int gm = m0 + row;
            int v = (gm < N_NODES);
            const float* src = g_h + (size_t)(v ? gm : 0) * HIDDEN + k0 + kv;
            unsigned int dst = (unsigned int)__cvta_generic_to_shared(dstb + row * SA_STRIDE + kv);
            int sz = v ? 16 : 0;
            asm volatile("cp.async.cg.shared.global [%0], [%1], 16, %2;"
                         :: "r"(dst), "l"(src), "r"(sz));
        }
        asm volatile("cp.async.commit_group;");
    };

    float acc[2][8][4];
#pragma unroll
    for (int mt = 0; mt < 2; mt++)
#pragma unroll
        for (int nt = 0; nt < 8; nt++)
#pragma unroll
            for (int i = 0; i < 4; i++) acc[mt][nt][i] = 0.0f;

    load_a(0);
    load_a(1);
    __syncthreads();   // sW ready (also orders first cp.async batch issue)

    const int NT = HIDDEN / 32;  // 8
    for (int t = 0; t < NT; t++) {
        if (t + 1 < NT) { asm volatile("cp.async.wait_group 1;"); }
        else            { asm volatile("cp.async.wait_group 0;"); }
        __syncthreads();

        const float* sA = sAb[t & 1];
#pragma unroll
        for (int kk = 0; kk < 4; kk++) {
            const int kb = kk * 8;
            unsigned int af[2][4], bf[8][2];
#pragma unroll
            for (int mt = 0; mt < 2; mt++) {
                const unsigned int* base = (const unsigned int*)(sA + (wid * 32 + mt * 16 + r) * SA_STRIDE + kb + c);
                af[mt][0] = base[0];
                af[mt][1] = base[8 * SA_STRIDE];
                af[mt][2] = base[4];
                af[mt][3] = base[8 * SA_STRIDE + 4];
            }
#pragma unroll
            for (int nt = 0; nt < 8; nt++) {
                const unsigned int* base = (const unsigned int*)(sW + (t * 32 + kb + c) * G2_SW_ST + nt * 8 + r);
                bf[nt][0] = base[0];
                bf[nt][1] = base[4 * G2_SW_ST];
            }
#pragma unroll
            for (int mt = 0; mt < 2; mt++)
#pragma unroll
                for (int nt = 0; nt < 8; nt++) {
                    asm volatile(
                        "mma.sync.aligned.m16n8k8.row.col.f32.tf32.tf32.f32 "
                        "{%0,%1,%2,%3}, {%4,%5,%6,%7}, {%8,%9}, {%0,%1,%2,%3};\n"
                        : "+f"(acc[mt][nt][0]), "+f"(acc[mt][nt][1]),
                          "+f"(acc[mt][nt][2]), "+f"(acc[mt][nt][3])
                        : "r"(af[mt][0]), "r"(af[mt][1]), "r"(af[mt][2]), "r"(af[mt][3]),
                          "r"(bf[nt][0]), "r"(bf[nt][1]));
                }
        }
        __syncthreads();
        if (t + 2 < NT) load_a(t + 2);
    }

    // epilogue: bias + fp16 bufA (pad cols zeroed) + hidden = temp[0]*v
    float t0 = temp[0];
#pragma unroll
    for (int mt = 0; mt < 2; mt++) {
#pragma unroll
        for (int hh = 0; hh < 2; hh++) {
            int gm = m0 + wid * 32 + mt * 16 + hh * 8 + r;
            if (gm >= N_NODES) continue;
            __half* arow = g_bufA + (size_t)gm * C_PAD;
            float* hrow = g_hidden + (size_t)gm * C_OUT;
#pragma unroll
            for (int nt = 0; nt < 8; nt++) {
                int col = nt * 8 + c * 2;
                if (col < C_OUT) {
                    float v0 = acc[mt][nt][hh * 2 + 0] + __ldg(b2 + col);
                    float v1 = acc[mt][nt][hh * 2 + 1] + __ldg(b2 + col + 1);
                    *(half2*)(arow + col) = __floats2half2_rn(v0, v1);
                    hrow[col] = t0 * v0;
                    hrow[col + 1] = t0 * v1;
                } else {
                    *(half2*)(arow + col) = __floats2half2_rn(0.f, 0.f);
                }
            }
        }
    }
}

// ---------------- pull hop 1: bufB[d] = sum w * bufA[src] ----------------
__global__ void __launch_bounds__(256) pull1_kernel() {
    int node = (blockIdx.x * blockDim.x + threadIdx.x) >> 5;
    int lane = threadIdx.x & 31;
    if (node >= N_NODES) return;
    int beg = g_rowptr[node], end = g_rowptr[node + 1];
    float a0 = 0.f, a1 = 0.f;
    int e = beg;
    for (; e + 3 < end; e += 4) {
        int2 e0 = g_csr[e], e1 = g_csr[e + 1], e2 = g_csr[e + 2], e3 = g_csr[e + 3];
        half2 h0 = *(const half2*)(g_bufA + (size_t)e0.x * C_PAD + lane * 2);
        half2 h1 = *(const half2*)(g_bufA + (size_t)e1.x * C_PAD + lane * 2);
        half2 h2 = *(const half2*)(g_bufA + (size_t)e2.x * C_PAD + lane * 2);
        half2 h3 = *(const half2*)(g_bufA + (size_t)e3.x * C_PAD + lane * 2);
        float2 f0 = __half22float2(h0), f1 = __half22float2(h1);
        float2 f2 = __half22float2(h2), f3 = __half22float2(h3);
        float w0 = __int_as_float(e0.y), w1 = __int_as_float(e1.y);
        float w2 = __int_as_float(e2.y), w3 = __int_as_float(e3.y);
        a0 += w0 * f0.x + w1 * f1.x + w2 * f2.x + w3 * f3.x;
        a1 += w0 * f0.y + w1 * f1.y + w2 * f2.y + w3 * f3.y;
    }
    for (; e < end; e++) {
        int2 ed = g_csr[e];
        half2 hv = *(const half2*)(g_bufA + (size_t)ed.x * C_PAD + lane * 2);
        float2 fv = __half22float2(hv);
        float w = __int_as_float(ed.y);
        a0 += w * fv.x;
        a1 += w * fv.y;
    }
    *(half2*)(g_bufB + (size_t)node * C_PAD + lane * 2) = __floats2half2_rn(a0, a1);
}

// ---------------- pull hop 2 + axpy ----------------
__global__ void __launch_bounds__(256) pull2_kernel(const float* __restrict__ temp, int kidx) {
    int node = (blockIdx.x * blockDim.x + threadIdx.x) >> 5;
    int lane = threadIdx.x & 31;
    if (node >= N_NODES) return;
    float t = temp[kidx];
    int beg = g_rowptr[node], end = g_rowptr[node + 1];
    float a0 = 0.f, a1 = 0.f;
    int e = beg;
    for (; e + 3 < end; e += 4) {
        int2 e0 = g_csr[e], e1 = g_csr[e + 1], e2 = g_csr[e + 2], e3 = g_csr[e + 3];
        half2 h0 = *(const half2*)(g_bufB + (size_t)e0.x * C_PAD + lane * 2);
        half2 h1 = *(const half2*)(g_bufB + (size_t)e1.x * C_PAD + lane * 2);
        half2 h2 = *(const half2*)(g_bufB + (size_t)e2.x * C_PAD + lane * 2);
        half2 h3 = *(const half2*)(g_bufB + (size_t)e3.x * C_PAD + lane * 2);
        float2 f0 = __half22float2(h0), f1 = __half22float2(h1);
        float2 f2 = __half22float2(h2), f3 = __half22float2(h3);
        float w0 = __int_as_float(e0.y), w1 = __int_as_float(e1.y);
        float w2 = __int_as_float(e2.y), w3 = __int_as_float(e3.y);
        a0 += w0 * f0.x + w1 * f1.x + w2 * f2.x + w3 * f3.x;
        a1 += w0 * f0.y + w1 * f1.y + w2 * f2.y + w3 * f3.y;
    }
    for (; e < end; e++) {
        int2 ed = g_csr[e];
        half2 hv = *(const half2*)(g_bufB + (size_t)ed.x * C_PAD + lane * 2);
        float2 fv = __half22float2(hv);
        float w = __int_as_float(ed.y);
        a0 += w * fv.x;
        a1 += w * fv.y;
    }
    *(half2*)(g_bufA + (size_t)node * C_PAD + lane * 2) = __floats2half2_rn(a0, a1);
    if (lane < C_OUT / 2) {
        float* hrow = g_hidden + (size_t)node * C_OUT + lane * 2;
        hrow[0] += t * a0;
        hrow[1] += t * a1;
    }
}

// ---------------- log_softmax ----------------
__global__ void __launch_bounds__(256) logsoftmax_kernel(float* __restrict__ out) {
    int node = (blockIdx.x * blockDim.x + threadIdx.x) >> 5;
    int lane = threadIdx.x & 31;
    if (node >= N_NODES) return;
    const float* row = g_hidden + (size_t)node * C_OUT;
    float v0 = row[lane];
    float v1 = (lane < C_OUT - 32) ? row[lane + 32] : -INFINITY;
    float m = fmaxf(v0, v1);
#pragma unroll
    for (int o = 16; o > 0; o >>= 1) m = fmaxf(m, __shfl_xor_sync(0xffffffffu, m, o));
    float s = expf(v0 - m) + ((lane < C_OUT - 32) ? expf(v1 - m) : 0.f);
#pragma unroll
    for (int o = 16; o > 0; o >>= 1) s += __shfl_xor_sync(0xffffffffu, s, o);
    float l = m + logf(s);
    float* orow = out + (size_t)node * C_OUT;
    orow[lane] = v0 - l;
    if (lane < C_OUT - 32) orow[lane + 32] = v1 - l;
}

// ---------------- launch ----------------
extern "C" void kernel_launch(void* const* d_in, const int* in_sizes, int n_in,
                              void* d_out, int out_size) {
    const float* x    = (const float*)d_in[0];
    const int*   ei   = (const int*)d_in[1];
    const float* W1   = (const float*)d_in[2];
    const float* b1   = (const float*)d_in[3];
    const float* W2   = (const float*)d_in[4];
    const float* b2   = (const float*)d_in[5];
    const float* temp = (const float*)d_in[6];
    float* out = (float*)d_out;

    int nb_nodes = (N_NODES + 255) / 256;
    int nb_edges = (N_EDGES + 255) / 256;

    static int attr_set = 0;
    if (!attr_set) {
        cudaFuncSetAttribute(gemm1_tc_kernel, cudaFuncAttributeMaxDynamicSharedMemorySize, GEMM1_SMEM);
        cudaFuncSetAttribute(gemm2_tc_kernel, cudaFuncAttributeMaxDynamicSharedMemorySize, G2_SMEM);
        attr_set = 1;
    }

    zero_kernel<<<nb_nodes, 256>>>();                                        // 0
    count_kernel<<<nb_edges, 256>>>(ei);                                     // 1
    gemm1_tc_kernel<<<(N_NODES + 63) / 64, 256, GEMM1_SMEM>>>(x, W1, b1);    // 2
    gemm2_tc_kernel<<<(N_NODES + 127) / 128, 128, G2_SMEM>>>(W2, b2, temp);  // 3 <- profiled
    dinv_kernel<<<nb_nodes, 256>>>();                                        // 4
    scan_partial_kernel<<<NB_SCAN, 256>>>();                                 // 5
    scan_offsets_kernel<<<1, 1>>>();                                         // 6
    scan_final_kernel<<<NB_SCAN, 256>>>();                                   // 7
    fill_kernel<<<nb_edges, 256>>>(ei);                                      // 8

    int pull_grid = (N_NODES * 32 + 255) / 256;
    for (int k = 0; k < K_HALF; k++) {
        pull1_kernel<<<pull_grid, 256>>>();
        pull2_kernel<<<pull_grid, 256>>>(temp, k + 1);
    }

    logsoftmax_kernel<<<pull_grid, 256>>>(out);
}

// round 8
// speedup vs baseline: 2.1022x; 1.0828x over previous
#include <cuda_runtime.h>
#include <cuda_fp16.h>
#include <cstdint>
#include <math.h>

#define N_NODES 100000
#define N_EDGES 1600000
#define C_IN 500
#define HIDDEN 256
#define C_OUT 50
#define C_PAD 64
#define K_HALF 5
#define NB_SCAN 391

// ---------------- scratch (static device globals; no allocation) ----------------
__device__ __half g_bufA[N_NODES * C_PAD];
__device__ __half g_bufB[N_NODES * C_PAD];
__device__ float  g_hidden[5000000];
__device__ float  g_dinv[N_NODES];
__device__ int    g_cnt_src[N_NODES];
__device__ int    g_cnt_dst[N_NODES];
__device__ int    g_cursor[N_NODES];
__device__ int    g_rowptr[N_NODES + 1];
__device__ int2   g_csr[N_EDGES];
__device__ int    g_partial[512];

// ---------------- graph preprocessing ----------------
__global__ void zero_kernel() {
    int i = blockIdx.x * blockDim.x + threadIdx.x;
    if (i < N_NODES) { g_cnt_src[i] = 0; g_cnt_dst[i] = 0; g_cursor[i] = 0; }
}

__global__ void count_kernel(const int* __restrict__ ei) {
    int i = blockIdx.x * blockDim.x + threadIdx.x;
    if (i < N_EDGES) {
        atomicAdd(&g_cnt_src[ei[i]], 1);
        atomicAdd(&g_cnt_dst[ei[N_EDGES + i]], 1);
    }
}

__global__ void dinv_kernel() {
    int i = blockIdx.x * blockDim.x + threadIdx.x;
    if (i < N_NODES) {
        int d = g_cnt_src[i];
        g_dinv[i] = d > 0 ? rsqrtf((float)d) : 0.0f;
    }
}

__global__ void scan_partial_kernel() {
    __shared__ int sh[256];
    int i = blockIdx.x * 256 + threadIdx.x;
    int v = (i < N_NODES) ? g_cnt_dst[i] : 0;
    sh[threadIdx.x] = v;
    __syncthreads();
    for (int s = 128; s > 0; s >>= 1) {
        if (threadIdx.x < s) sh[threadIdx.x] += sh[threadIdx.x + s];
        __syncthreads();
    }
    if (threadIdx.x == 0) g_partial[blockIdx.x] = sh[0];
}

__global__ void scan_offsets_kernel() {
    int acc = 0;
    for (int b = 0; b < NB_SCAN; b++) { int v = g_partial[b]; g_partial[b] = acc; acc += v; }
    g_rowptr[N_NODES] = N_EDGES;
}

__global__ void scan_final_kernel() {
    __shared__ int sh[256];
    int i = blockIdx.x * 256 + threadIdx.x;
    int v = (i < N_NODES) ? g_cnt_dst[i] : 0;
    sh[threadIdx.x] = v;
    __syncthreads();
    for (int s = 1; s < 256; s <<= 1) {
        int t = (threadIdx.x >= s) ? sh[threadIdx.x - s] : 0;
        __syncthreads();
        sh[threadIdx.x] += t;
        __syncthreads();
    }
    if (i < N_NODES) g_rowptr[i] = g_partial[blockIdx.x] + sh[threadIdx.x] - v;
}

__global__ void fill_kernel(const int* __restrict__ ei) {
    int i = blockIdx.x * blockDim.x + threadIdx.x;
    if (i < N_EDGES) {
        int s = ei[i], d = ei[N_EDGES + i];
        int pos = g_rowptr[d] + atomicAdd(&g_cursor[d], 1);
        float w = g_dinv[s] * g_dinv[d];
        g_csr[pos] = make_int2(s, __float_as_int(w));
    }
}

// ---------------- FUSED GEMM1+GEMM2 ----------------
// h = relu(x@W1+b1) kept in smem (fp16); out = h@W2+b2 -> bufA(fp16) + hidden=temp[0]*v.
#define SA_STRIDE 36
#define SB_STRIDE 264
#define A_SZ (64 * SA_STRIDE)
#define B_SZ (32 * SB_STRIDE)
#define GEMM_SMEM (2 * (A_SZ + B_SZ) * 4)  /* 86016 bytes */
#define SH_ST 264                           /* halves */

__global__ void __launch_bounds__(256) gemm12_tc_kernel(
    const float* __restrict__ A, const float* __restrict__ W, const float* __restrict__ bias,
    const float* __restrict__ W2, const float* __restrict__ b2, const float* __restrict__ temp) {
    extern __shared__ float smem[];
    float* sAb[2] = { smem, smem + A_SZ + B_SZ };
    float* sBb[2] = { smem + A_SZ, smem + 2 * A_SZ + B_SZ };

    const int tid = threadIdx.x;
    const int m0 = blockIdx.x * 64;
    const int wid = tid >> 5, lane = tid & 31;
    const int warp_m = wid >> 2, warp_n = wid & 3;
    const int r = lane >> 2, c = lane & 3;

    float acc[2][8][4];
#pragma unroll
    for (int mt = 0; mt < 2; mt++)
#pragma unroll
        for (int nt = 0; nt < 8; nt++)
#pragma unroll
            for (int i = 0; i < 4; i++) acc[mt][nt][i] = 0.0f;

    auto load_tiles = [&](int buf, int k0) {
#pragma unroll
        for (int j = 0; j < 2; j++) {
            int idx = tid + j * 256;
            int row = idx >> 3, kv = (idx & 7) * 4;
            int gm = m0 + row, gk = k0 + kv;
            int v = (gm < N_NODES) && (gk < C_IN);
            const float* src = A + (size_t)(v ? gm : 0) * C_IN + (v ? gk : 0);
            unsigned int dst = (unsigned int)__cvta_generic_to_shared(sAb[buf] + row * SA_STRIDE + kv);
            int sz = v ? 16 : 0;
            asm volatile("cp.async.cg.shared.global [%0], [%1], 16, %2;\n"
                         :: "r"(dst), "l"(src), "r"(sz));
        }
#pragma unroll
        for (int j = 0; j < 8; j++) {
            int idx = tid + j * 256;
            int krow = idx >> 6, nv = (idx & 63) * 4;
            int gk = k0 + krow;
            int v = (gk < C_IN);
            const float* src = W + (size_t)(v ? gk : 0) * HIDDEN + nv;
            unsigned int dst = (unsigned int)__cvta_generic_to_shared(sBb[buf] + krow * SB_STRIDE + nv);
            int sz = v ? 16 : 0;
            asm volatile("cp.async.cg.shared.global [%0], [%1], 16, %2;\n"
                         :: "r"(dst), "l"(src), "r"(sz));
        }
        asm volatile("cp.async.commit_group;\n");
    };

    const int NIT = (C_IN + 31) / 32;
    load_tiles(0, 0);

    for (int it = 0; it < NIT; it++) {
        if (it + 1 < NIT) {
            load_tiles((it + 1) & 1, (it + 1) * 32);
            asm volatile("cp.async.wait_group 1;\n");
        } else {
            asm volatile("cp.async.wait_group 0;\n");
        }
        __syncthreads();

        const float* sA = sAb[it & 1];
        const float* sB = sBb[it & 1];

#pragma unroll
        for (int kk = 0; kk < 4; kk++) {
            const int kb = kk * 8;
            unsigned int af[2][4], bf[8][2];
#pragma unroll
            for (int mt = 0; mt < 2; mt++) {
                const unsigned int* base = (const unsigned int*)(sA + (warp_m * 32 + mt * 16 + r) * SA_STRIDE + kb + c);
                af[mt][0] = base[0];
                af[mt][1] = base[8 * SA_STRIDE];
                af[mt][2] = base[4];
                af[mt][3] = base[8 * SA_STRIDE + 4];
            }
#pragma unroll
            for (int nt = 0; nt < 8; nt++) {
                const unsigned int* base = (const unsigned int*)(sB + (kb + c) * SB_STRIDE + warp_n * 64 + nt * 8 + r);
                bf[nt][0] = base[0];
                bf[nt][1] = base[4 * SB_STRIDE];
            }
#pragma unroll
            for (int mt = 0; mt < 2; mt++)
#pragma unroll
                for (int nt = 0; nt < 8; nt++) {
                    asm volatile(
                        "mma.sync.aligned.m16n8k8.row.col.f32.tf32.tf32.f32 "
                        "{%0,%1,%2,%3}, {%4,%5,%6,%7}, {%8,%9}, {%0,%1,%2,%3};\n"
                        : "+f"(acc[mt][nt][0]), "+f"(acc[mt][nt][1]),
                          "+f"(acc[mt][nt][2]), "+f"(acc[mt][nt][3])
                        : "r"(af[mt][0]), "r"(af[mt][1]), "r"(af[mt][2]), "r"(af[mt][3]),
                          "r"(bf[nt][0]), "r"(bf[nt][1]));
                }
        }
        __syncthreads();
    }
    // NOTE: final loop iteration ends with __syncthreads(); smem buffers now dead.

    // ---- stage h tile (bias1 + relu, fp16) and W2^T (fp16) into smem ----
    __half* sH   = (__half*)smem;            // [64][SH_ST]
    __half* sW2t = (__half*)smem + 64 * SH_ST; // [64 n][SH_ST k]

#pragma unroll
    for (int mt = 0; mt < 2; mt++) {
#pragma unroll
        for (int nt = 0; nt < 8; nt++) {
            int col = warp_n * 64 + nt * 8 + c * 2;
            float2 bv = *(const float2*)(bias + col);
            int row0 = warp_m * 32 + mt * 16 + r;
            float v0 = fmaxf(acc[mt][nt][0] + bv.x, 0.f);
            float v1 = fmaxf(acc[mt][nt][1] + bv.y, 0.f);
            *(half2*)(sH + row0 * SH_ST + col) = __floats2half2_rn(v0, v1);
            float v2 = fmaxf(acc[mt][nt][2] + bv.x, 0.f);
            float v3 = fmaxf(acc[mt][nt][3] + bv.y, 0.f);
            *(half2*)(sH + (row0 + 8) * SH_ST + col) = __floats2half2_rn(v2, v3);
        }
    }
    // W2^T: sW2t[n][k] = W2[k][n], zero-pad n>=50
    for (int idx = tid; idx < 64 * 256; idx += 256) {
        int n = idx >> 8, k = idx & 255;
        float v = (n < C_OUT) ? __ldg(W2 + (size_t)k * C_OUT + n) : 0.f;
        sW2t[n * SH_ST + k] = __float2half_rn(v);
    }
    __syncthreads();

    // ---- second GEMM: out[64x64] = h @ W2 (fp16 mma, f32 accum) ----
    float acc2[2][2][4];
#pragma unroll
    for (int mt = 0; mt < 2; mt++)
#pragma unroll
        for (int nt = 0; nt < 2; nt++)
#pragma unroll
            for (int i = 0; i < 4; i++) acc2[mt][nt][i] = 0.0f;

#pragma unroll
    for (int ks = 0; ks < 16; ks++) {
        unsigned int a[2][4], b[2][2];
#pragma unroll
        for (int mt = 0; mt < 2; mt++) {
            int row = warp_m * 32 + mt * 16 + r;
            const unsigned int* p0 = (const unsigned int*)(sH + row * SH_ST + ks * 16 + 2 * c);
            const unsigned int* p1 = (const unsigned int*)(sH + (row + 8) * SH_ST + ks * 16 + 2 * c);
            a[mt][0] = p0[0];
            a[mt][1] = p1[0];
            a[mt][2] = p0[4];
            a[mt][3] = p1[4];
        }
#pragma unroll
        for (int nt = 0; nt < 2; nt++) {
            int n = warp_n * 16 + nt * 8 + r;
            const unsigned int* q = (const unsigned int*)(sW2t + n * SH_ST + ks * 16 + 2 * c);
            b[nt][0] = q[0];
            b[nt][1] = q[4];
        }
#pragma unroll
        for (int mt = 0; mt < 2; mt++)
#pragma unroll
            for (int nt = 0; nt < 2; nt++) {
                asm volatile(
                    "mma.sync.aligned.m16n8k16.row.col.f32.f16.f16.f32 "
                    "{%0,%1,%2,%3}, {%4,%5,%6,%7}, {%8,%9}, {%0,%1,%2,%3};\n"
                    : "+f"(acc2[mt][nt][0]), "+f"(acc2[mt][nt][1]),
                      "+f"(acc2[mt][nt][2]), "+f"(acc2[mt][nt][3])
                    : "r"(a[mt][0]), "r"(a[mt][1]), "r"(a[mt][2]), "r"(a[mt][3]),
                      "r"(b[nt][0]), "r"(b[nt][1]));
            }
    }

    // ---- epilogue2: bias2, fp16 bufA (pad cols zeroed), hidden = temp[0]*v ----
    float t0 = __ldg(temp);
#pragma unroll
    for (int mt = 0; mt < 2; mt++) {
#pragma unroll
        for (int nt = 0; nt < 2; nt++) {
            int col = warp_n * 16 + nt * 8 + c * 2;
#pragma unroll
            for (int hh = 0; hh < 2; hh++) {
                int gm = m0 + warp_m * 32 + mt * 16 + hh * 8 + r;
                if (gm >= N_NODES) continue;
                __half* arow = g_bufA + (size_t)gm * C_PAD;
                if (col < C_OUT) {
                    float v0 = acc2[mt][nt][hh * 2 + 0] + __ldg(b2 + col);
                    float v1 = acc2[mt][nt][hh * 2 + 1] + __ldg(b2 + col + 1);
                    *(half2*)(arow + col) = __floats2half2_rn(v0, v1);
                    float* hrow = g_hidden + (size_t)gm * C_OUT + col;
                    hrow[0] = t0 * v0;
                    hrow[1] = t0 * v1;
                } else {
                    *(half2*)(arow + col) = __floats2half2_rn(0.f, 0.f);
                }
            }
        }
    }
}

// ---------------- pull hop 1: bufB[d] = sum w * bufA[src] ----------------
__global__ void __launch_bounds__(256) pull1_kernel() {
    int node = (blockIdx.x * blockDim.x + threadIdx.x) >> 5;
    int lane = threadIdx.x & 31;
    if (node >= N_NODES) return;
    int beg = g_rowptr[node], end = g_rowptr[node + 1];
    float a0 = 0.f, a1 = 0.f;
    int e = beg;
    for (; e + 3 < end; e += 4) {
        int2 e0 = g_csr[e], e1 = g_csr[e + 1], e2 = g_csr[e + 2], e3 = g_csr[e + 3];
        half2 h0 = *(const half2*)(g_bufA + (size_t)e0.x * C_PAD + lane * 2);
        half2 h1 = *(const half2*)(g_bufA + (size_t)e1.x * C_PAD + lane * 2);
        half2 h2 = *(const half2*)(g_bufA + (size_t)e2.x * C_PAD + lane * 2);
        half2 h3 = *(const half2*)(g_bufA + (size_t)e3.x * C_PAD + lane * 2);
        float2 f0 = __half22float2(h0), f1 = __half22float2(h1);
        float2 f2 = __half22float2(h2), f3 = __half22float2(h3);
        float w0 = __int_as_float(e0.y), w1 = __int_as_float(e1.y);
        float w2 = __int_as_float(e2.y), w3 = __int_as_float(e3.y);
        a0 += w0 * f0.x + w1 * f1.x + w2 * f2.x + w3 * f3.x;
        a1 += w0 * f0.y + w1 * f1.y + w2 * f2.y + w3 * f3.y;
    }
    for (; e < end; e++) {
        int2 ed = g_csr[e];
        half2 hv = *(const half2*)(g_bufA + (size_t)ed.x * C_PAD + lane * 2);
        float2 fv = __half22float2(hv);
        float w = __int_as_float(ed.y);
        a0 += w * fv.x;
        a1 += w * fv.y;
    }
    *(half2*)(g_bufB + (size_t)node * C_PAD + lane * 2) = __floats2half2_rn(a0, a1);
}

// ---------------- pull hop 2 + axpy ----------------
__global__ void __launch_bounds__(256) pull2_kernel(const float* __restrict__ temp, int kidx) {
    int node = (blockIdx.x * blockDim.x + threadIdx.x) >> 5;
    int lane = threadIdx.x & 31;
    if (node >= N_NODES) return;
    float t = temp[kidx];
    int beg = g_rowptr[node], end = g_rowptr[node + 1];
    float a0 = 0.f, a1 = 0.f;
    int e = beg;
    for (; e + 3 < end; e += 4) {
        int2 e0 = g_csr[e], e1 = g_csr[e + 1], e2 = g_csr[e + 2], e3 = g_csr[e + 3];
        half2 h0 = *(const half2*)(g_bufB + (size_t)e0.x * C_PAD + lane * 2);
        half2 h1 = *(const half2*)(g_bufB + (size_t)e1.x * C_PAD + lane * 2);
        half2 h2 = *(const half2*)(g_bufB + (size_t)e2.x * C_PAD + lane * 2);
        half2 h3 = *(const half2*)(g_bufB + (size_t)e3.x * C_PAD + lane * 2);
        float2 f0 = __half22float2(h0), f1 = __half22float2(h1);
        float2 f2 = __half22float2(h2), f3 = __half22float2(h3);
        float w0 = __int_as_float(e0.y), w1 = __int_as_float(e1.y);
        float w2 = __int_as_float(e2.y), w3 = __int_as_float(e3.y);
        a0 += w0 * f0.x + w1 * f1.x + w2 * f2.x + w3 * f3.x;
        a1 += w0 * f0.y + w1 * f1.y + w2 * f2.y + w3 * f3.y;
    }
    for (; e < end; e++) {
        int2 ed = g_csr[e];
        half2 hv = *(const half2*)(g_bufB + (size_t)ed.x * C_PAD + lane * 2);
        float2 fv = __half22float2(hv);
        float w = __int_as_float(ed.y);
        a0 += w * fv.x;
        a1 += w * fv.y;
    }
    *(half2*)(g_bufA + (size_t)node * C_PAD + lane * 2) = __floats2half2_rn(a0, a1);
    if (lane < C_OUT / 2) {
        float* hrow = g_hidden + (size_t)node * C_OUT + lane * 2;
        hrow[0] += t * a0;
        hrow[1] += t * a1;
    }
}

// ---------------- log_softmax ----------------
__global__ void __launch_bounds__(256) logsoftmax_kernel(float* __restrict__ out) {
    int node = (blockIdx.x * blockDim.x + threadIdx.x) >> 5;
    int lane = threadIdx.x & 31;
    if (node >= N_NODES) return;
    const float* row = g_hidden + (size_t)node * C_OUT;
    float v0 = row[lane];
    float v1 = (lane < C_OUT - 32) ? row[lane + 32] : -INFINITY;
    float m = fmaxf(v0, v1);
#pragma unroll
    for (int o = 16; o > 0; o >>= 1) m = fmaxf(m, __shfl_xor_sync(0xffffffffu, m, o));
    float s = expf(v0 - m) + ((lane < C_OUT - 32) ? expf(v1 - m) : 0.f);
#pragma unroll
    for (int o = 16; o > 0; o >>= 1) s += __shfl_xor_sync(0xffffffffu, s, o);
    float l = m + logf(s);
    float* orow = out + (size_t)node * C_OUT;
    orow[lane] = v0 - l;
    if (lane < C_OUT - 32) orow[lane + 32] = v1 - l;
}

// ---------------- launch ----------------
extern "C" void kernel_launch(void* const* d_in, const int* in_sizes, int n_in,
                              void* d_out, int out_size) {
    const float* x    = (const float*)d_in[0];
    const int*   ei   = (const int*)d_in[1];
    const float* W1   = (const float*)d_in[2];
    const float* b1   = (const float*)d_in[3];
    const float* W2   = (const float*)d_in[4];
    const float* b2   = (const float*)d_in[5];
    const float* temp = (const float*)d_in[6];
    float* out = (float*)d_out;

    int nb_nodes = (N_NODES + 255) / 256;
    int nb_edges = (N_EDGES + 255) / 256;

    static int attr_set = 0;
    if (!attr_set) {
        cudaFuncSetAttribute(gemm12_tc_kernel, cudaFuncAttributeMaxDynamicSharedMemorySize, GEMM_SMEM);
        attr_set = 1;
    }

    zero_kernel<<<nb_nodes, 256>>>();                                         // 0
    count_kernel<<<nb_edges, 256>>>(ei);                                      // 1
    dinv_kernel<<<nb_nodes, 256>>>();                                         // 2
    gemm12_tc_kernel<<<(N_NODES + 63) / 64, 256, GEMM_SMEM>>>(x, W1, b1, W2, b2, temp);  // 3 <- profiled
    scan_partial_kernel<<<NB_SCAN, 256>>>();                                  // 4
    scan_offsets_kernel<<<1, 1>>>();                                          // 5
    scan_final_kernel<<<NB_SCAN, 256>>>();                                    // 6
    fill_kernel<<<nb_edges, 256>>>(ei);                                       // 7

    int pull_grid = (N_NODES * 32 + 255) / 256;
    for (int k = 0; k < K_HALF; k++) {
        pull1_kernel<<<pull_grid, 256>>>();
        pull2_kernel<<<pull_grid, 256>>>(temp, k + 1);
    }

    logsoftmax_kernel<<<pull_grid, 256>>>(out);
}

// round 10
// speedup vs baseline: 2.2191x; 1.0556x over previous
#include <cuda_runtime.h>
#include <cuda_fp16.h>
#include <cstdint>
#include <math.h>

#define N_NODES 100000
#define N_EDGES 1600000
#define C_IN 500
#define HIDDEN 256
#define C_OUT 50
#define C_PAD 64
#define K_HALF 5
#define NB_SCAN 391

// ---------------- scratch (static device globals; no allocation) ----------------
__device__ __half g_w1h[256 * 512];        // W1^T fp16 padded: [n=256][k=512]
__device__ __half g_bufA[N_NODES * C_PAD];
__device__ __half g_bufB[N_NODES * C_PAD];
__device__ float  g_hidden[5000000];
__device__ float  g_dinv[N_NODES];
__device__ int    g_cnt_src[N_NODES];
__device__ int    g_cnt_dst[N_NODES];
__device__ int    g_cursor[N_NODES];
__device__ int    g_rowptr[N_NODES + 1];
__device__ int2   g_csr[N_EDGES];
__device__ int    g_partial[512];

// ---------------- graph preprocessing ----------------
__global__ void zero_kernel() {
    int i = blockIdx.x * blockDim.x + threadIdx.x;
    if (i < N_NODES) { g_cnt_src[i] = 0; g_cnt_dst[i] = 0; g_cursor[i] = 0; }
}

__global__ void count_kernel(const int* __restrict__ ei) {
    int i = blockIdx.x * blockDim.x + threadIdx.x;
    if (i < N_EDGES) {
        atomicAdd(&g_cnt_src[ei[i]], 1);
        atomicAdd(&g_cnt_dst[ei[N_EDGES + i]], 1);
    }
}

__global__ void dinv_kernel() {
    int i = blockIdx.x * blockDim.x + threadIdx.x;
    if (i < N_NODES) {
        int d = g_cnt_src[i];
        g_dinv[i] = d > 0 ? rsqrtf((float)d) : 0.0f;
    }
}

__global__ void scan_partial_kernel() {
    __shared__ int sh[256];
    int i = blockIdx.x * 256 + threadIdx.x;
    int v = (i < N_NODES) ? g_cnt_dst[i] : 0;
    sh[threadIdx.x] = v;
    __syncthreads();
    for (int s = 128; s > 0; s >>= 1) {
        if (threadIdx.x < s) sh[threadIdx.x] += sh[threadIdx.x + s];
        __syncthreads();
    }
    if (threadIdx.x == 0) g_partial[blockIdx.x] = sh[0];
}

__global__ void scan_offsets_kernel() {
    int acc = 0;
    for (int b = 0; b < NB_SCAN; b++) { int v = g_partial[b]; g_partial[b] = acc; acc += v; }
    g_rowptr[N_NODES] = N_EDGES;
}

__global__ void scan_final_kernel() {
    __shared__ int sh[256];
    int i = blockIdx.x * 256 + threadIdx.x;
    int v = (i < N_NODES) ? g_cnt_dst[i] : 0;
    sh[threadIdx.x] = v;
    __syncthreads();
    for (int s = 1; s < 256; s <<= 1) {
        int t = (threadIdx.x >= s) ? sh[threadIdx.x - s] : 0;
        __syncthreads();
        sh[threadIdx.x] += t;
        __syncthreads();
    }
    if (i < N_NODES) g_rowptr[i] = g_partial[blockIdx.x] + sh[threadIdx.x] - v;
}

__global__ void fill_kernel(const int* __restrict__ ei) {
    int i = blockIdx.x * blockDim.x + threadIdx.x;
    if (i < N_EDGES) {
        int s = ei[i], d = ei[N_EDGES + i];
        int pos = g_rowptr[d] + atomicAdd(&g_cursor[d], 1);
        float w = g_dinv[s] * g_dinv[d];
        g_csr[pos] = make_int2(s, __float_as_int(w));
    }
}

// ---------------- W1 -> fp16 transposed scratch: g_w1h[n][k] ----------------
__global__ void w1cvt_kernel(const float* __restrict__ W1) {
    int idx = blockIdx.x * 256 + threadIdx.x;
    if (idx < 256 * 512) {
        int n = idx >> 9, k = idx & 511;
        float v = (k < C_IN) ? W1[(size_t)k * HIDDEN + n] : 0.f;
        g_w1h[idx] = __float2half_rn(v);
    }
}

// ---------------- FUSED GEMM1+GEMM2 (fp16 mma mainloop) ----------------
// h = relu(x@W1+b1) in smem (fp16); out = h@W2+b2 -> bufA(fp16) + hidden=temp[0]*v.
// Mainloop: BM=64, BN=256, BK=32, fp16 m16n8k16, f32 accum.
#define A16_ST 72   /* halves: bank(m,c)=(36m+c)%32=(4m+c)%32, conflict-free for r/c pattern */
#define B16_ST 40   /* halves: 32 data + 8 pad */
#define A16_BYTES (64 * A16_ST * 2)    /* 9216 */
#define B16_BYTES (256 * B16_ST * 2)   /* 20480 */
#define SH_ST 264
#define GEMM_SMEM (2 * 64 * SH_ST * 2) /* 67584: phase-2 h + W2t, covers mainloop 2*(9216+20480)=59392 */

__global__ void __launch_bounds__(256) gemm12_tc_kernel(
    const float* __restrict__ A, const float* __restrict__ bias,
    const float* __restrict__ W2, const float* __restrict__ b2, const float* __restrict__ temp) {
    extern __shared__ float smem[];
    __half* smh = (__half*)smem;
    __half* sAb[2] = { smh, smh + (A16_BYTES + B16_BYTES) / 2 };
    __half* sBb[2] = { smh + A16_BYTES / 2, smh + (2 * A16_BYTES + B16_BYTES) / 2 };

    const int tid = threadIdx.x;
    const int m0 = blockIdx.x * 64;
    const int wid = tid >> 5, lane = tid & 31;
    const int warp_m = wid >> 2, warp_n = wid & 3;
    const int r = lane >> 2, c = lane & 3;

    float acc[2][8][4];
#pragma unroll
    for (int mt = 0; mt < 2; mt++)
#pragma unroll
        for (int nt = 0; nt < 8; nt++)
#pragma unroll
            for (int i = 0; i < 4; i++) acc[mt][nt][i] = 0.0f;

    // A staging regs: 2 float4/thread (64x32 floats / 256 threads)
    float4 astg[2];

    auto ldgA = [&](int t) {
        int k0 = t * 32;
#pragma unroll
        for (int j = 0; j < 2; j++) {
            int idx = tid + j * 256;
            int row = idx >> 3, kv = (idx & 7) * 4;
            int gm = m0 + row, gk = k0 + kv;
            if (gm < N_NODES && gk < C_IN) {
                astg[j] = *(const float4*)(A + (size_t)gm * C_IN + gk);
            } else {
                astg[j] = make_float4(0.f, 0.f, 0.f, 0.f);
            }
        }
    };
    auto stsA = [&](int t) {
        __half* dstb = sAb[t & 1];
#pragma unroll
        for (int j = 0; j < 2; j++) {
            int idx = tid + j * 256;
            int row = idx >> 3, kv = (idx & 7) * 4;
            half2 h0 = __floats2half2_rn(astg[j].x, astg[j].y);
            half2 h1 = __floats2half2_rn(astg[j].z, astg[j].w);
            uint2 p;
            p.x = *reinterpret_cast<unsigned int*>(&h0);
            p.y = *reinterpret_cast<unsigned int*>(&h1);
            *(uint2*)(dstb + row * A16_ST + kv) = p;
        }
    };
    auto cpB = [&](int t) {
        __half* dstb = sBb[t & 1];
        int k0 = t * 32;
#pragma unroll
        for (int j = 0; j < 4; j++) {
            int idx = tid + j * 256;
            int n = idx >> 2, part = idx & 3;   // 4 x 16B chunks of 8 halves per row
            const __half* src = g_w1h + (size_t)n * 512 + k0 + part * 8;
            unsigned int dst = (unsigned int)__cvta_generic_to_shared(dstb + n * B16_ST + part * 8);
            asm volatile("cp.async.cg.shared.global [%0], [%1], 16, 16;"
                         :: "r"(dst), "l"(src));
        }
        asm volatile("cp.async.commit_group;");
    };

    const int NT = 16;   // 16 x 32 = 512 >= 500

    ldgA(0);
    stsA(0);
    cpB(0);
    ldgA(1);

    for (int t = 0; t < NT; t++) {
        if (t + 1 < NT) {
            stsA(t + 1);
            cpB(t + 1);
            if (t + 2 < NT) ldgA(t + 2);
            asm volatile("cp.async.wait_group 1;");
        } else {
            asm volatile("cp.async.wait_group 0;");
        }
        __syncthreads();

        const __half* sA = sAb[t & 1];
        const __half* sB = sBb[t & 1];
#pragma unroll
        for (int ks = 0; ks < 2; ks++) {
            const int kb = ks * 16;
            unsigned int af[2][4], bf[8][2];
#pragma unroll
            for (int mt = 0; mt < 2; mt++) {
                int row = warp_m * 32 + mt * 16 + r;
                const unsigned int* p0 = (const unsigned int*)(sA + row * A16_ST + kb) + c;
                const unsigned int* p1 = (const unsigned int*)(sA + (row + 8) * A16_ST + kb) + c;
                af[mt][0] = p0[0];
                af[mt][1] = p1[0];
                af[mt][2] = p0[4];
                af[mt][3] = p1[4];
            }
#pragma unroll
            for (int nt = 0; nt < 8; nt++) {
                int n = warp_n * 64 + nt * 8 + r;
                const unsigned int* q = (const unsigned int*)(sB + n * B16_ST + kb) + c;
                bf[nt][0] = q[0];
                bf[nt][1] = q[4];
            }
#pragma unroll
            for (int mt = 0; mt < 2; mt++)
#pragma unroll
                for (int nt = 0; nt < 8; nt++) {
                    asm volatile(
                        "mma.sync.aligned.m16n8k16.row.col.f32.f16.f16.f32 "
                        "{%0,%1,%2,%3}, {%4,%5,%6,%7}, {%8,%9}, {%0,%1,%2,%3};\n"
                        : "+f"(acc[mt][nt][0]), "+f"(acc[mt][nt][1]),
                          "+f"(acc[mt][nt][2]), "+f"(acc[mt][nt][3])
                        : "r"(af[mt][0]), "r"(af[mt][1]), "r"(af[mt][2]), "r"(af[mt][3]),
                          "r"(bf[nt][0]), "r"(bf[nt][1]));
                }
        }
        __syncthreads();
    }

    // ---- stage h tile (bias1 + relu, fp16) and W2^T (fp16) into smem ----
    __half* sH   = smh;                 // [64][SH_ST]
    __half* sW2t = smh + 64 * SH_ST;    // [64 n][SH_ST k]

#pragma unroll
    for (int mt = 0; mt < 2; mt++) {
#pragma unroll
        for (int nt = 0; nt < 8; nt++) {
            int col = warp_n * 64 + nt * 8 + c * 2;
            float2 bv = *(const float2*)(bias + col);
            int row0 = warp_m * 32 + mt * 16 + r;
            float v0 = fmaxf(acc[mt][nt][0] + bv.x, 0.f);
            float v1 = fmaxf(acc[mt][nt][1] + bv.y, 0.f);
            *(half2*)(sH + row0 * SH_ST + col) = __floats2half2_rn(v0, v1);
            float v2 = fmaxf(acc[mt][nt][2] + bv.x, 0.f);
            float v3 = fmaxf(acc[mt][nt][3] + bv.y, 0.f);
            *(half2*)(sH + (row0 + 8) * SH_ST + col) = __floats2half2_rn(v2, v3);
        }
    }
    for (int idx = tid; idx < 64 * 256; idx += 256) {
        int n = idx >> 8, k = idx & 255;
        float v = (n < C_OUT) ? __ldg(W2 + (size_t)k * C_OUT + n) : 0.f;
        sW2t[n * SH_ST + k] = __float2half_rn(v);
    }
    __syncthreads();

    // ---- second GEMM: out[64x64] = h @ W2 (fp16 mma, f32 accum) ----
    float acc2[2][2][4];
#pragma unroll
    for (int mt = 0; mt < 2; mt++)
#pragma unroll
        for (int nt = 0; nt < 2; nt++)
#pragma unroll
            for (int i = 0; i < 4; i++) acc2[mt][nt][i] = 0.0f;

#pragma unroll
    for (int ks = 0; ks < 16; ks++) {
        unsigned int a[2][4], b[2][2];
#pragma unroll
        for (int mt = 0; mt < 2; mt++) {
            int row = warp_m * 32 + mt * 16 + r;
            const unsigned int* p0 = (const unsigned int*)(sH + row * SH_ST + ks * 16 + 2 * c);
            const unsigned int* p1 = (const unsigned int*)(sH + (row + 8) * SH_ST + ks * 16 + 2 * c);
            a[mt][0] = p0[0];
            a[mt][1] = p1[0];
            a[mt][2] = p0[4];
            a[mt][3] = p1[4];
        }
#pragma unroll
        for (int nt = 0; nt < 2; nt++) {
            int n = warp_n * 16 + nt * 8 + r;
            const unsigned int* q = (const unsigned int*)(sW2t + n * SH_ST + ks * 16 + 2 * c);
            b[nt][0] = q[0];
            b[nt][1] = q[4];
        }
#pragma unroll
        for (int mt = 0; mt < 2; mt++)
#pragma unroll
            for (int nt = 0; nt < 2; nt++) {
                asm volatile(
                    "mma.sync.aligned.m16n8k16.row.col.f32.f16.f16.f32 "
                    "{%0,%1,%2,%3}, {%4,%5,%6,%7}, {%8,%9}, {%0,%1,%2,%3};\n"
                    : "+f"(acc2[mt][nt][0]), "+f"(acc2[mt][nt][1]),
                      "+f"(acc2[mt][nt][2]), "+f"(acc2[mt][nt][3])
                    : "r"(a[mt][0]), "r"(a[mt][1]), "r"(a[mt][2]), "r"(a[mt][3]),
                      "r"(b[nt][0]), "r"(b[nt][1]));
            }
    }

    // ---- epilogue2: bias2, fp16 bufA (pad cols zeroed), hidden = temp[0]*v ----
    float t0 = __ldg(temp);
#pragma unroll
    for (int mt = 0; mt < 2; mt++) {
#pragma unroll
        for (int nt = 0; nt < 2; nt++) {
            int col = warp_n * 16 + nt * 8 + c * 2;
#pragma unroll
            for (int hh = 0; hh < 2; hh++) {
                int gm = m0 + warp_m * 32 + mt * 16 + hh * 8 + r;
                if (gm >= N_NODES) continue;
                __half* arow = g_bufA + (size_t)gm * C_PAD;
                if (col < C_OUT) {
                    float v0 = acc2[mt][nt][hh * 2 + 0] + __ldg(b2 + col);
                    float v1 = acc2[mt][nt][hh * 2 + 1] + __ldg(b2 + col + 1);
                    *(half2*)(arow + col) = __floats2half2_rn(v0, v1);
                    float* hrow = g_hidden + (size_t)gm * C_OUT + col;
                    hrow[0] = t0 * v0;
                    hrow[1] = t0 * v1;
                } else {
                    *(half2*)(arow + col) = __floats2half2_rn(0.f, 0.f);
                }
            }
        }
    }
}

// ---------------- pull hop 1: bufB[d] = sum w * bufA[src] ----------------
__global__ void __launch_bounds__(256) pull1_kernel() {
    int node = (blockIdx.x * blockDim.x + threadIdx.x) >> 5;
    int lane = threadIdx.x & 31;
    if (node >= N_NODES) return;
    int beg = g_rowptr[node], end = g_rowptr[node + 1];
    float a0 = 0.f, a1 = 0.f;
    int e = beg;
    for (; e + 3 < end; e += 4) {
        int2 e0 = g_csr[e], e1 = g_csr[e + 1], e2 = g_csr[e + 2], e3 = g_csr[e + 3];
        half2 h0 = *(const half2*)(g_bufA + (size_t)e0.x * C_PAD + lane * 2);
        half2 h1 = *(const half2*)(g_bufA + (size_t)e1.x * C_PAD + lane * 2);
        half2 h2 = *(const half2*)(g_bufA + (size_t)e2.x * C_PAD + lane * 2);
        half2 h3 = *(const half2*)(g_bufA + (size_t)e3.x * C_PAD + lane * 2);
        float2 f0 = __half22float2(h0), f1 = __half22float2(h1);
        float2 f2 = __half22float2(h2), f3 = __half22float2(h3);
        float w0 = __int_as_float(e0.y), w1 = __int_as_float(e1.y);
        float w2 = __int_as_float(e2.y), w3 = __int_as_float(e3.y);
        a0 += w0 * f0.x + w1 * f1.x + w2 * f2.x + w3 * f3.x;
        a1 += w0 * f0.y + w1 * f1.y + w2 * f2.y + w3 * f3.y;
    }
    for (; e < end; e++) {
        int2 ed = g_csr[e];
        half2 hv = *(const half2*)(g_bufA + (size_t)ed.x * C_PAD + lane * 2);
        float2 fv = __half22float2(hv);
        float w = __int_as_float(ed.y);
        a0 += w * fv.x;
        a1 += w * fv.y;
    }
    *(half2*)(g_bufB + (size_t)node * C_PAD + lane * 2) = __floats2half2_rn(a0, a1);
}

// ---------------- pull hop 2 + axpy ----------------
__global__ void __launch_bounds__(256) pull2_kernel(const float* __restrict__ temp, int kidx) {
    int node = (blockIdx.x * blockDim.x + threadIdx.x) >> 5;
    int lane = threadIdx.x & 31;
    if (node >= N_NODES) return;
    float t = temp[kidx];
    int beg = g_rowptr[node], end = g_rowptr[node + 1];
    float a0 = 0.f, a1 = 0.f;
    int e = beg;
    for (; e + 3 < end; e += 4) {
        int2 e0 = g_csr[e], e1 = g_csr[e + 1], e2 = g_csr[e + 2], e3 = g_csr[e + 3];
        half2 h0 = *(const half2*)(g_bufB + (size_t)e0.x * C_PAD + lane * 2);
        half2 h1 = *(const half2*)(g_bufB + (size_t)e1.x * C_PAD + lane * 2);
        half2 h2 = *(const half2*)(g_bufB + (size_t)e2.x * C_PAD + lane * 2);
        half2 h3 = *(const half2*)(g_bufB + (size_t)e3.x * C_PAD + lane * 2);
        float2 f0 = __half22float2(h0), f1 = __half22float2(h1);
        float2 f2 = __half22float2(h2), f3 = __half22float2(h3);
        float w0 = __int_as_float(e0.y), w1 = __int_as_float(e1.y);
        float w2 = __int_as_float(e2.y), w3 = __int_as_float(e3.y);
        a0 += w0 * f0.x + w1 * f1.x + w2 * f2.x + w3 * f3.x;
        a1 += w0 * f0.y + w1 * f1.y + w2 * f2.y + w3 * f3.y;
    }
    for (; e < end; e++) {
        int2 ed = g_csr[e];
        half2 hv = *(const half2*)(g_bufB + (size_t)ed.x * C_PAD + lane * 2);
        float2 fv = __half22float2(hv);
        float w = __int_as_float(ed.y);
        a0 += w * fv.x;
        a1 += w * fv.y;
    }
    *(half2*)(g_bufA + (size_t)node * C_PAD + lane * 2) = __floats2half2_rn(a0, a1);
    if (lane < C_OUT / 2) {
        float* hrow = g_hidden + (size_t)node * C_OUT + lane * 2;
        hrow[0] += t * a0;
        hrow[1] += t * a1;
    }
}

// ---------------- log_softmax ----------------
__global__ void __launch_bounds__(256) logsoftmax_kernel(float* __restrict__ out) {
    int node = (blockIdx.x * blockDim.x + threadIdx.x) >> 5;
    int lane = threadIdx.x & 31;
    if (node >= N_NODES) return;
    const float* row = g_hidden + (size_t)node * C_OUT;
    float v0 = row[lane];
    float v1 = (lane < C_OUT - 32) ? row[lane + 32] : -INFINITY;
    float m = fmaxf(v0, v1);
#pragma unroll
    for (int o = 16; o > 0; o >>= 1) m = fmaxf(m, __shfl_xor_sync(0xffffffffu, m, o));
    float s = expf(v0 - m) + ((lane < C_OUT - 32) ? expf(v1 - m) : 0.f);
#pragma unroll
    for (int o = 16; o > 0; o >>= 1) s += __shfl_xor_sync(0xffffffffu, s, o);
    float l = m + logf(s);
    float* orow = out + (size_t)node * C_OUT;
    orow[lane] = v0 - l;
    if (lane < C_OUT - 32) orow[lane + 32] = v1 - l;
}

// ---------------- launch ----------------
extern "C" void kernel_launch(void* const* d_in, const int* in_sizes, int n_in,
                              void* d_out, int out_size) {
    const float* x    = (const float*)d_in[0];
    const int*   ei   = (const int*)d_in[1];
    const float* W1   = (const float*)d_in[2];
    const float* b1   = (const float*)d_in[3];
    const float* W2   = (const float*)d_in[4];
    const float* b2   = (const float*)d_in[5];
    const float* temp = (const float*)d_in[6];
    float* out = (float*)d_out;

    int nb_nodes = (N_NODES + 255) / 256;
    int nb_edges = (N_EDGES + 255) / 256;

    static int attr_set = 0;
    if (!attr_set) {
        cudaFuncSetAttribute(gemm12_tc_kernel, cudaFuncAttributeMaxDynamicSharedMemorySize, GEMM_SMEM);
        attr_set = 1;
    }

    w1cvt_kernel<<<512, 256>>>(W1);                                           // 0
    zero_kernel<<<nb_nodes, 256>>>();                                         // 1
    count_kernel<<<nb_edges, 256>>>(ei);                                      // 2
    gemm12_tc_kernel<<<(N_NODES + 63) / 64, 256, GEMM_SMEM>>>(x, b1, W2, b2, temp);  // 3 <- profiled
    dinv_kernel<<<nb_nodes, 256>>>();                                         // 4
    scan_partial_kernel<<<NB_SCAN, 256>>>();                                  // 5
    scan_offsets_kernel<<<1, 1>>>();                                          // 6
    scan_final_kernel<<<NB_SCAN, 256>>>();                                    // 7
    fill_kernel<<<nb_edges, 256>>>(ei);                                       // 8

    int pull_grid = (N_NODES * 32 + 255) / 256;
    for (int k = 0; k < K_HALF; k++) {
        pull1_kernel<<<pull_grid, 256>>>();
        pull2_kernel<<<pull_grid, 256>>>(temp, k + 1);
    }

    logsoftmax_kernel<<<pull_grid, 256>>>(out);
}